// round 5
// baseline (speedup 1.0000x reference)
#include <cuda_runtime.h>
#include <math.h>

#define NN 20000
#define FEAT 128
#define HID 32
#define HEADS 8
#define HC 256          // HEADS*HID
#define CLS 40
#define E_IN 640000
#define TOT (E_IN + NN)
#define NEG 0.2f

// ---------------- scratch (device globals; no allocation allowed) ----------------
__device__ float g_h1[NN * HC];       // layer1 linear output
__device__ float g_h2[NN * HC];       // layer1 GAT output after ELU
__device__ float g_as1[NN * HEADS];
__device__ float g_ad1[NN * HEADS];
__device__ float g_g2[NN * CLS];      // layer2 linear output
__device__ float g_as2[NN];
__device__ float g_ad2[NN];
__device__ int   g_rowptr[NN + 1];
__device__ int   g_cnt[NN];
__device__ int   g_cur[NN];
__device__ int   g_esrc[TOT];         // src node per CSR slot (sorted by dst)

// ---------------- helpers (edge_index is INT32; loads always in-bounds) ----------------
__device__ __forceinline__ int edge_src(const int* ei, int e) {
    int idx = (e < E_IN) ? e : 0;
    int v = ei[idx];
    return (e < E_IN) ? v : (e - E_IN);
}
__device__ __forceinline__ int edge_dst(const int* ei, int e) {
    int idx = (e < E_IN) ? (E_IN + e) : 0;
    int v = ei[idx];
    return (e < E_IN) ? v : (e - E_IN);
}
__device__ __forceinline__ float lrelu(float v) { return v > 0.0f ? v : NEG * v; }

// ---------------- init ----------------
__global__ void k_init() {
    int t = blockIdx.x * blockDim.x + threadIdx.x;
    if (t < NN) g_cnt[t] = 0;
}

// ---------------- CSR build (int atomics only) ----------------
__global__ void k_count(const int* __restrict__ ei) {
    int t = blockIdx.x * blockDim.x + threadIdx.x;
    if (t >= TOT) return;
    atomicAdd(&g_cnt[edge_dst(ei, t)], 1);
}

// Chunked exclusive scan: thread t owns elements [t*CH, t*CH+CH).
__global__ void k_scan() {
    const int CH = (NN + 1023) / 1024;            // 20
    __shared__ int sm[1024];
    int tid = threadIdx.x;
    int base = tid * CH;

    int sum = 0;
    for (int j = 0; j < CH; j++) {
        int i = base + j;
        int idx = (i < NN) ? i : 0;
        int v = g_cnt[idx];
        if (i >= NN) v = 0;
        sum += v;
    }
    sm[tid] = sum;
    __syncthreads();

    for (int off = 1; off < 1024; off <<= 1) {
        int idx = (tid >= off) ? (tid - off) : tid;   // always valid
        int t2 = sm[idx];
        if (tid < off) t2 = 0;
        __syncthreads();
        sm[tid] += t2;
        __syncthreads();
    }

    int run = sm[tid] - sum;                      // exclusive prefix of this chunk
    for (int j = 0; j < CH; j++) {
        int i = base + j;
        if (i < NN) {
            g_rowptr[i] = run;
            g_cur[i] = run;
            run += g_cnt[i];
        }
    }
    if (tid == 1023) g_rowptr[NN] = sm[1023];
}

__global__ void k_scatter(const int* __restrict__ ei) {
    int t = blockIdx.x * blockDim.x + threadIdx.x;
    if (t >= TOT) return;
    int d = edge_dst(ei, t);
    int s = edge_src(ei, t);
    int pos = atomicAdd(&g_cur[d], 1);
    g_esrc[pos] = s;
}

// ---------------- GEMM1: x[NN,FEAT] @ W1[FEAT,HC] -> g_h1 ----------------
__global__ void k_gemm1(const float* __restrict__ A, const float* __restrict__ B) {
    const int BM = 64, BN = 64, BK = 16, NT = 256;
    __shared__ __align__(16) float As[BM][BK];
    __shared__ __align__(16) float Bs[BK][BN];
    int tid = threadIdx.x;
    int tn = tid % 16;          // BN/4
    int tm = tid / 16;
    int row0 = blockIdx.x * BM;
    int col0 = blockIdx.y * BN;
    float acc[4][4] = {};
    for (int k0 = 0; k0 < FEAT; k0 += BK) {
        for (int i = tid; i < BM * BK; i += NT) {
            int r = i / BK, c = i % BK;
            int gr = row0 + r;
            int ga = (gr < NN) ? (gr * FEAT + k0 + c) : 0;
            float v = A[ga];
            As[r][c] = (gr < NN) ? v : 0.0f;
        }
        for (int i = tid; i < BK * BN; i += NT) {
            int r = i / BN, c = i % BN;
            Bs[r][c] = B[(k0 + r) * HC + col0 + c];
        }
        __syncthreads();
#pragma unroll
        for (int k = 0; k < BK; k++) {
            float a0 = As[tm * 4 + 0][k];
            float a1 = As[tm * 4 + 1][k];
            float a2 = As[tm * 4 + 2][k];
            float a3 = As[tm * 4 + 3][k];
            float4 bv = *(const float4*)&Bs[k][tn * 4];
            acc[0][0] += a0 * bv.x; acc[0][1] += a0 * bv.y; acc[0][2] += a0 * bv.z; acc[0][3] += a0 * bv.w;
            acc[1][0] += a1 * bv.x; acc[1][1] += a1 * bv.y; acc[1][2] += a1 * bv.z; acc[1][3] += a1 * bv.w;
            acc[2][0] += a2 * bv.x; acc[2][1] += a2 * bv.y; acc[2][2] += a2 * bv.z; acc[2][3] += a2 * bv.w;
            acc[3][0] += a3 * bv.x; acc[3][1] += a3 * bv.y; acc[3][2] += a3 * bv.z; acc[3][3] += a3 * bv.w;
        }
        __syncthreads();
    }
#pragma unroll
    for (int i = 0; i < 4; i++) {
        int gr = row0 + tm * 4 + i;
        if (gr >= NN) continue;
#pragma unroll
        for (int j = 0; j < 4; j++)
            g_h1[gr * HC + col0 + tn * 4 + j] = acc[i][j];
    }
}

// ---------------- GEMM2: g_h2[NN,HC] @ W2[HC,CLS] -> g_g2 ----------------
__global__ void k_gemm2(const float* __restrict__ B) {
    const int BM = 64, BN = 40, BK = 16, NT = 160;
    __shared__ __align__(16) float As[BM][BK];
    __shared__ __align__(16) float Bs[BK][BN];
    int tid = threadIdx.x;
    int tn = tid % 10;          // BN/4
    int tm = tid / 10;
    int row0 = blockIdx.x * BM;
    float acc[4][4] = {};
    for (int k0 = 0; k0 < HC; k0 += BK) {
        for (int i = tid; i < BM * BK; i += NT) {
            int r = i / BK, c = i % BK;
            int gr = row0 + r;
            int ga = (gr < NN) ? (gr * HC + k0 + c) : 0;
            float v = g_h2[ga];
            As[r][c] = (gr < NN) ? v : 0.0f;
        }
        for (int i = tid; i < BK * BN; i += NT) {
            int r = i / BN, c = i % BN;
            Bs[r][c] = B[(k0 + r) * CLS + c];
        }
        __syncthreads();
#pragma unroll
        for (int k = 0; k < BK; k++) {
            float a0 = As[tm * 4 + 0][k];
            float a1 = As[tm * 4 + 1][k];
            float a2 = As[tm * 4 + 2][k];
            float a3 = As[tm * 4 + 3][k];
            float4 bv = *(const float4*)&Bs[k][tn * 4];
            acc[0][0] += a0 * bv.x; acc[0][1] += a0 * bv.y; acc[0][2] += a0 * bv.z; acc[0][3] += a0 * bv.w;
            acc[1][0] += a1 * bv.x; acc[1][1] += a1 * bv.y; acc[1][2] += a1 * bv.z; acc[1][3] += a1 * bv.w;
            acc[2][0] += a2 * bv.x; acc[2][1] += a2 * bv.y; acc[2][2] += a2 * bv.z; acc[2][3] += a2 * bv.w;
            acc[3][0] += a3 * bv.x; acc[3][1] += a3 * bv.y; acc[3][2] += a3 * bv.z; acc[3][3] += a3 * bv.w;
        }
        __syncthreads();
    }
#pragma unroll
    for (int i = 0; i < 4; i++) {
        int gr = row0 + tm * 4 + i;
        if (gr >= NN) continue;
#pragma unroll
        for (int j = 0; j < 4; j++)
            g_g2[gr * CLS + tn * 4 + j] = acc[i][j];
    }
}

// ---------------- layer1 alpha projections ----------------
__global__ void k_alpha1(const float* __restrict__ a1s, const float* __restrict__ a1d) {
    int t = blockIdx.x * blockDim.x + threadIdx.x;
    if (t >= NN * HEADS) return;
    int n = t >> 3, h = t & 7;
    const float* hp = &g_h1[n * HC + h * HID];
    const float* ap = &a1s[h * HID];
    const float* dp = &a1d[h * HID];
    float accS = 0.0f, accD = 0.0f;
#pragma unroll
    for (int c = 0; c < HID; c++) {
        float hv = hp[c];
        accS += hv * ap[c];
        accD += hv * dp[c];
    }
    g_as1[t] = accS;
    g_ad1[t] = accD;
}

// ---------------- layer1: softmax (CSR-local) + aggregation + bias + ELU ----------------
// One block per dst node; warp h handles head h (8 warps = 256 threads).
__global__ void k_agg1(const float* __restrict__ b1) {
    int n = blockIdx.x;
    int h = threadIdx.x >> 5;
    int lane = threadIdx.x & 31;
    int beg = g_rowptr[n], end = g_rowptr[n + 1];
    float ad = g_ad1[n * HEADS + h];

    // pass 1: max over incoming edges
    float m = -INFINITY;
    for (int i = beg + lane; i < end; i += 32) {
        int s = g_esrc[i];
        m = fmaxf(m, lrelu(g_as1[s * HEADS + h] + ad));
    }
#pragma unroll
    for (int o = 16; o; o >>= 1) m = fmaxf(m, __shfl_xor_sync(0xffffffffu, m, o));

    // pass 2: sum of exp
    float ssum = 0.0f;
    for (int i = beg + lane; i < end; i += 32) {
        int s = g_esrc[i];
        ssum += __expf(lrelu(g_as1[s * HEADS + h] + ad) - m);
    }
#pragma unroll
    for (int o = 16; o; o >>= 1) ssum += __shfl_xor_sync(0xffffffffu, ssum, o);
    float inv_s = 1.0f / ssum;

    // pass 3: weighted gather of h rows; lane = channel within head
    float acc = 0.0f;
    for (int i0 = beg; i0 < end; i0 += 32) {
        int i = i0 + lane;
        int sl = 0;
        float wl = 0.0f;
        if (i < end) {
            sl = g_esrc[i];
            wl = __expf(lrelu(g_as1[sl * HEADS + h] + ad) - m) * inv_s;
        }
        int lim = min(32, end - i0);
        for (int j = 0; j < lim; j++) {
            float w  = __shfl_sync(0xffffffffu, wl, j);
            int   s2 = __shfl_sync(0xffffffffu, sl, j);
            acc += w * g_h1[s2 * HC + h * HID + lane];
        }
    }
    float o = acc + b1[h * HID + lane];
    g_h2[n * HC + h * HID + lane] = (o > 0.0f) ? o : (__expf(o) - 1.0f);   // ELU
}

// ---------------- layer2 alpha projections ----------------
__global__ void k_alpha2(const float* __restrict__ a2s, const float* __restrict__ a2d) {
    int n = blockIdx.x * blockDim.x + threadIdx.x;
    if (n >= NN) return;
    const float* gp = &g_g2[n * CLS];
    float accS = 0.0f, accD = 0.0f;
#pragma unroll
    for (int c = 0; c < CLS; c++) {
        float gv = gp[c];
        accS += gv * a2s[c];
        accD += gv * a2d[c];
    }
    g_as2[n] = accS;
    g_ad2[n] = accD;
}

// ---------------- layer2: softmax (CSR-local) + aggregation + bias + log_softmax ----------------
// One block (64 threads) per dst node.
__global__ void k_agg2(const float* __restrict__ b2, float* __restrict__ out) {
    int n = blockIdx.x;
    int t = threadIdx.x;
    __shared__ float red[64];
    __shared__ int   s_src[64];
    __shared__ float s_w[64];
    int beg = g_rowptr[n], end = g_rowptr[n + 1];
    float ad = g_ad2[n];

    // pass 1: max
    float m = -INFINITY;
    for (int i = beg + t; i < end; i += 64)
        m = fmaxf(m, lrelu(g_as2[g_esrc[i]] + ad));
    red[t] = m; __syncthreads();
    for (int off = 32; off; off >>= 1) { if (t < off) red[t] = fmaxf(red[t], red[t + off]); __syncthreads(); }
    m = red[0]; __syncthreads();

    // pass 2: sum of exp
    float ssum = 0.0f;
    for (int i = beg + t; i < end; i += 64)
        ssum += __expf(lrelu(g_as2[g_esrc[i]] + ad) - m);
    red[t] = ssum; __syncthreads();
    for (int off = 32; off; off >>= 1) { if (t < off) red[t] += red[t + off]; __syncthreads(); }
    float inv_s = 1.0f / red[0];
    __syncthreads();

    // pass 3: weighted gather, 64-edge chunks staged in shared
    float acc = 0.0f;
    for (int i0 = beg; i0 < end; i0 += 64) {
        int i = i0 + t;
        if (i < end) {
            int s = g_esrc[i];
            s_src[t] = s;
            s_w[t] = __expf(lrelu(g_as2[s] + ad) - m) * inv_s;
        }
        __syncthreads();
        int lim = min(64, end - i0);
        if (t < CLS)
            for (int j = 0; j < lim; j++)
                acc += s_w[j] * g_g2[s_src[j] * CLS + t];
        __syncthreads();
    }

    float o = (t < CLS) ? (acc + b2[t]) : -INFINITY;
    red[t] = o; __syncthreads();
    for (int off = 32; off; off >>= 1) { if (t < off) red[t] = fmaxf(red[t], red[t + off]); __syncthreads(); }
    float mx = red[0]; __syncthreads();
    red[t] = (t < CLS) ? __expf(o - mx) : 0.0f;
    __syncthreads();
    for (int off = 32; off; off >>= 1) { if (t < off) red[t] += red[t + off]; __syncthreads(); }
    if (t < CLS) out[n * CLS + t] = o - mx - logf(red[0]);
}

// ---------------- launch ----------------
extern "C" void kernel_launch(void* const* d_in, const int* in_sizes, int n_in,
                              void* d_out, int out_size) {
    const float* x   = (const float*)d_in[0];
    const int*   ei  = (const int*)d_in[1];      // edge_index is int32 (JAX x64 disabled)
    const float* W1  = (const float*)d_in[2];
    const float* a1s = (const float*)d_in[3];
    const float* a1d = (const float*)d_in[4];
    const float* b1  = (const float*)d_in[5];
    const float* W2  = (const float*)d_in[6];
    const float* a2s = (const float*)d_in[7];
    const float* a2d = (const float*)d_in[8];
    const float* b2  = (const float*)d_in[9];
    float*       out = (float*)d_out;

    // CSR build
    k_init<<<(NN + 255) / 256, 256>>>();
    k_count<<<(TOT + 255) / 256, 256>>>(ei);
    k_scan<<<1, 1024>>>();
    k_scatter<<<(TOT + 255) / 256, 256>>>(ei);

    // layer 1
    k_gemm1<<<dim3((NN + 63) / 64, HC / 64), 256>>>(x, W1);
    k_alpha1<<<(NN * HEADS + 255) / 256, 256>>>(a1s, a1d);
    k_agg1<<<NN, 256>>>(b1);

    // layer 2
    k_gemm2<<<(NN + 63) / 64, 160>>>(W2);
    k_alpha2<<<(NN + 255) / 256, 256>>>(a2s, a2d);
    k_agg2<<<NN, 64>>>(b2, out);
}

// round 6
// speedup vs baseline: 1.1893x; 1.1893x over previous
#include <cuda_runtime.h>
#include <math.h>

#define NN 20000
#define FEAT 128
#define HID 32
#define HEADS 8
#define HC 256          // HEADS*HID
#define CLS 40
#define E_IN 640000
#define TOT (E_IN + NN)
#define NEG 0.2f

// ---------------- scratch (device globals; no allocation allowed) ----------------
__device__ float g_h1[NN * HC];       // layer1 linear output
__device__ float g_h2[NN * HC];       // layer1 GAT output after ELU
__device__ float g_as1[NN * HEADS];
__device__ float g_ad1[NN * HEADS];
__device__ float g_g2[NN * CLS];      // layer2 linear output
__device__ float g_as2[NN];
__device__ float g_ad2[NN];
__device__ int   g_rowptr[NN + 1];
__device__ int   g_cnt[NN];
__device__ int   g_cur[NN];
__device__ int   g_esrc[TOT];         // src node per CSR slot (sorted by dst)

// ---------------- helpers (edge_index is INT32; loads always in-bounds) ----------------
__device__ __forceinline__ int edge_src(const int* ei, int e) {
    int idx = (e < E_IN) ? e : 0;
    int v = ei[idx];
    return (e < E_IN) ? v : (e - E_IN);
}
__device__ __forceinline__ int edge_dst(const int* ei, int e) {
    int idx = (e < E_IN) ? (E_IN + e) : 0;
    int v = ei[idx];
    return (e < E_IN) ? v : (e - E_IN);
}
__device__ __forceinline__ float lrelu(float v) { return v > 0.0f ? v : NEG * v; }

// ---------------- init ----------------
__global__ void k_init() {
    int t = blockIdx.x * blockDim.x + threadIdx.x;
    if (t < NN) g_cnt[t] = 0;
}

// ---------------- CSR build (int atomics only) ----------------
__global__ void k_count(const int* __restrict__ ei) {
    int t = blockIdx.x * blockDim.x + threadIdx.x;
    if (t >= TOT) return;
    atomicAdd(&g_cnt[edge_dst(ei, t)], 1);
}

// Chunked exclusive scan: thread t owns elements [t*CH, t*CH+CH).
__global__ void k_scan() {
    const int CH = (NN + 1023) / 1024;            // 20
    __shared__ int sm[1024];
    int tid = threadIdx.x;
    int base = tid * CH;

    int sum = 0;
    for (int j = 0; j < CH; j++) {
        int i = base + j;
        int idx = (i < NN) ? i : 0;
        int v = g_cnt[idx];
        if (i >= NN) v = 0;
        sum += v;
    }
    sm[tid] = sum;
    __syncthreads();

    for (int off = 1; off < 1024; off <<= 1) {
        int idx = (tid >= off) ? (tid - off) : tid;   // always valid
        int t2 = sm[idx];
        if (tid < off) t2 = 0;
        __syncthreads();
        sm[tid] += t2;
        __syncthreads();
    }

    int run = sm[tid] - sum;                      // exclusive prefix of this chunk
    for (int j = 0; j < CH; j++) {
        int i = base + j;
        if (i < NN) {
            g_rowptr[i] = run;
            g_cur[i] = run;
            run += g_cnt[i];
        }
    }
    if (tid == 1023) g_rowptr[NN] = sm[1023];
}

__global__ void k_scatter(const int* __restrict__ ei) {
    int t = blockIdx.x * blockDim.x + threadIdx.x;
    if (t >= TOT) return;
    int d = edge_dst(ei, t);
    int s = edge_src(ei, t);
    int pos = atomicAdd(&g_cur[d], 1);
    g_esrc[pos] = s;
}

// ---------------- GEMM1: x[NN,FEAT] @ W1[FEAT,HC] -> g_h1 ----------------
// 128x64 tile, BK=16, 256 threads, 8x4 per-thread microtile, float4 loads.
__global__ __launch_bounds__(256) void k_gemm1(const float* __restrict__ A,
                                               const float* __restrict__ B) {
    const int BM = 128, BN = 64, BK = 16;
    __shared__ __align__(16) float As[BK][BM];   // transposed: As[k][m]
    __shared__ __align__(16) float Bs[BK][BN];
    int tid = threadIdx.x;
    int tn = tid & 15;          // 0..15 : column group (4 cols)
    int tm = tid >> 4;          // 0..15 : row group (8 rows)
    int row0 = blockIdx.x * BM;
    int col0 = blockIdx.y * BN;
    float acc[8][4] = {};

    for (int k0 = 0; k0 < FEAT; k0 += BK) {
        // A tile: 128 rows x 16 cols = 512 float4; 2 per thread; store transposed
#pragma unroll
        for (int j = 0; j < 2; j++) {
            int li = tid * 2 + j;           // 0..511
            int r = li >> 2;                // 0..127
            int c4 = li & 3;                // 0..3
            int gr = row0 + r;
            if (gr > NN - 1) gr = NN - 1;   // clamp: OOB rows guarded at store
            float4 v = *(const float4*)&A[gr * FEAT + k0 + c4 * 4];
            As[c4 * 4 + 0][r] = v.x;
            As[c4 * 4 + 1][r] = v.y;
            As[c4 * 4 + 2][r] = v.z;
            As[c4 * 4 + 3][r] = v.w;
        }
        // B tile: 16 x 64 = 256 float4; 1 per thread
        {
            int r = tid >> 4;               // 0..15
            int c4 = tid & 15;              // 0..15
            *(float4*)&Bs[r][c4 * 4] = *(const float4*)&B[(k0 + r) * HC + col0 + c4 * 4];
        }
        __syncthreads();
#pragma unroll
        for (int k = 0; k < BK; k++) {
            float a[8], b[4];
            *(float4*)&a[0] = *(const float4*)&As[k][tm * 8];
            *(float4*)&a[4] = *(const float4*)&As[k][tm * 8 + 4];
            *(float4*)&b[0] = *(const float4*)&Bs[k][tn * 4];
#pragma unroll
            for (int i = 0; i < 8; i++)
#pragma unroll
                for (int j = 0; j < 4; j++)
                    acc[i][j] += a[i] * b[j];
        }
        __syncthreads();
    }
#pragma unroll
    for (int i = 0; i < 8; i++) {
        int gr = row0 + tm * 8 + i;
        if (gr < NN)
            *(float4*)&g_h1[gr * HC + col0 + tn * 4] =
                make_float4(acc[i][0], acc[i][1], acc[i][2], acc[i][3]);
    }
}

// ---------------- GEMM2: g_h2[NN,HC] @ W2[HC,CLS] -> g_g2 ----------------
// BM=128, BN=40, BK=16, 320 threads, 4x4 per-thread microtile.
__global__ __launch_bounds__(320) void k_gemm2(const float* __restrict__ B) {
    const int BM = 128, BN = 40, BK = 16, NT = 320;
    __shared__ __align__(16) float As[BK][BM];   // transposed
    __shared__ __align__(16) float Bs[BK][BN];
    int tid = threadIdx.x;
    int tn = tid % 10;          // 0..9  : column group (4 cols)
    int tm = tid / 10;          // 0..31 : row group (4 rows)
    int row0 = blockIdx.x * BM;
    float acc[4][4] = {};

    for (int k0 = 0; k0 < HC; k0 += BK) {
        // A tile: 128 x 16 = 512 float4
        for (int li = tid; li < 512; li += NT) {
            int r = li >> 2;
            int c4 = li & 3;
            int gr = row0 + r;
            if (gr > NN - 1) gr = NN - 1;
            float4 v = *(const float4*)&g_h2[gr * HC + k0 + c4 * 4];
            As[c4 * 4 + 0][r] = v.x;
            As[c4 * 4 + 1][r] = v.y;
            As[c4 * 4 + 2][r] = v.z;
            As[c4 * 4 + 3][r] = v.w;
        }
        // B tile: 16 x 40 = 160 float4
        for (int li = tid; li < 160; li += NT) {
            int r = li / 10;
            int c4 = li % 10;
            *(float4*)&Bs[r][c4 * 4] = *(const float4*)&B[(k0 + r) * CLS + c4 * 4];
        }
        __syncthreads();
#pragma unroll
        for (int k = 0; k < BK; k++) {
            float a[4], b[4];
            *(float4*)&a[0] = *(const float4*)&As[k][tm * 4];
            *(float4*)&b[0] = *(const float4*)&Bs[k][tn * 4];
#pragma unroll
            for (int i = 0; i < 4; i++)
#pragma unroll
                for (int j = 0; j < 4; j++)
                    acc[i][j] += a[i] * b[j];
        }
        __syncthreads();
    }
#pragma unroll
    for (int i = 0; i < 4; i++) {
        int gr = row0 + tm * 4 + i;
        if (gr < NN)
            *(float4*)&g_g2[gr * CLS + tn * 4] =
                make_float4(acc[i][0], acc[i][1], acc[i][2], acc[i][3]);
    }
}

// ---------------- layer1 alpha projections ----------------
__global__ void k_alpha1(const float* __restrict__ a1s, const float* __restrict__ a1d) {
    int t = blockIdx.x * blockDim.x + threadIdx.x;
    if (t >= NN * HEADS) return;
    int n = t >> 3, h = t & 7;
    const float* hp = &g_h1[n * HC + h * HID];
    const float* ap = &a1s[h * HID];
    const float* dp = &a1d[h * HID];
    float accS = 0.0f, accD = 0.0f;
#pragma unroll
    for (int c = 0; c < HID; c++) {
        float hv = hp[c];
        accS += hv * ap[c];
        accD += hv * dp[c];
    }
    g_as1[t] = accS;
    g_ad1[t] = accD;
}

// ---------------- layer1: softmax (CSR-local) + aggregation + bias + ELU ----------------
// One block per dst node; warp h handles head h (8 warps = 256 threads).
__global__ void k_agg1(const float* __restrict__ b1) {
    int n = blockIdx.x;
    int h = threadIdx.x >> 5;
    int lane = threadIdx.x & 31;
    int beg = g_rowptr[n], end = g_rowptr[n + 1];
    float ad = g_ad1[n * HEADS + h];

    // pass 1: max over incoming edges
    float m = -INFINITY;
    for (int i = beg + lane; i < end; i += 32) {
        int s = g_esrc[i];
        m = fmaxf(m, lrelu(g_as1[s * HEADS + h] + ad));
    }
#pragma unroll
    for (int o = 16; o; o >>= 1) m = fmaxf(m, __shfl_xor_sync(0xffffffffu, m, o));

    // pass 2: sum of exp
    float ssum = 0.0f;
    for (int i = beg + lane; i < end; i += 32) {
        int s = g_esrc[i];
        ssum += __expf(lrelu(g_as1[s * HEADS + h] + ad) - m);
    }
#pragma unroll
    for (int o = 16; o; o >>= 1) ssum += __shfl_xor_sync(0xffffffffu, ssum, o);
    float inv_s = 1.0f / ssum;

    // pass 3: weighted gather of h rows; lane = channel within head
    float acc = 0.0f;
    for (int i0 = beg; i0 < end; i0 += 32) {
        int i = i0 + lane;
        int sl = 0;
        float wl = 0.0f;
        if (i < end) {
            sl = g_esrc[i];
            wl = __expf(lrelu(g_as1[sl * HEADS + h] + ad) - m) * inv_s;
        }
        int lim = min(32, end - i0);
        for (int j = 0; j < lim; j++) {
            float w  = __shfl_sync(0xffffffffu, wl, j);
            int   s2 = __shfl_sync(0xffffffffu, sl, j);
            acc += w * g_h1[s2 * HC + h * HID + lane];
        }
    }
    float o = acc + b1[h * HID + lane];
    g_h2[n * HC + h * HID + lane] = (o > 0.0f) ? o : (__expf(o) - 1.0f);   // ELU
}

// ---------------- layer2 alpha projections ----------------
__global__ void k_alpha2(const float* __restrict__ a2s, const float* __restrict__ a2d) {
    int n = blockIdx.x * blockDim.x + threadIdx.x;
    if (n >= NN) return;
    const float* gp = &g_g2[n * CLS];
    float accS = 0.0f, accD = 0.0f;
#pragma unroll
    for (int c = 0; c < CLS; c++) {
        float gv = gp[c];
        accS += gv * a2s[c];
        accD += gv * a2d[c];
    }
    g_as2[n] = accS;
    g_ad2[n] = accD;
}

// ---------------- layer2: softmax (CSR-local) + aggregation + bias + log_softmax ----------------
// One block (64 threads) per dst node.
__global__ void k_agg2(const float* __restrict__ b2, float* __restrict__ out) {
    int n = blockIdx.x;
    int t = threadIdx.x;
    __shared__ float red[64];
    __shared__ int   s_src[64];
    __shared__ float s_w[64];
    int beg = g_rowptr[n], end = g_rowptr[n + 1];
    float ad = g_ad2[n];

    // pass 1: max
    float m = -INFINITY;
    for (int i = beg + t; i < end; i += 64)
        m = fmaxf(m, lrelu(g_as2[g_esrc[i]] + ad));
    red[t] = m; __syncthreads();
    for (int off = 32; off; off >>= 1) { if (t < off) red[t] = fmaxf(red[t], red[t + off]); __syncthreads(); }
    m = red[0]; __syncthreads();

    // pass 2: sum of exp
    float ssum = 0.0f;
    for (int i = beg + t; i < end; i += 64)
        ssum += __expf(lrelu(g_as2[g_esrc[i]] + ad) - m);
    red[t] = ssum; __syncthreads();
    for (int off = 32; off; off >>= 1) { if (t < off) red[t] += red[t + off]; __syncthreads(); }
    float inv_s = 1.0f / red[0];
    __syncthreads();

    // pass 3: weighted gather, 64-edge chunks staged in shared
    float acc = 0.0f;
    for (int i0 = beg; i0 < end; i0 += 64) {
        int i = i0 + t;
        if (i < end) {
            int s = g_esrc[i];
            s_src[t] = s;
            s_w[t] = __expf(lrelu(g_as2[s] + ad) - m) * inv_s;
        }
        __syncthreads();
        int lim = min(64, end - i0);
        if (t < CLS)
            for (int j = 0; j < lim; j++)
                acc += s_w[j] * g_g2[s_src[j] * CLS + t];
        __syncthreads();
    }

    float o = (t < CLS) ? (acc + b2[t]) : -INFINITY;
    red[t] = o; __syncthreads();
    for (int off = 32; off; off >>= 1) { if (t < off) red[t] = fmaxf(red[t], red[t + off]); __syncthreads(); }
    float mx = red[0]; __syncthreads();
    red[t] = (t < CLS) ? __expf(o - mx) : 0.0f;
    __syncthreads();
    for (int off = 32; off; off >>= 1) { if (t < off) red[t] += red[t + off]; __syncthreads(); }
    if (t < CLS) out[n * CLS + t] = o - mx - logf(red[0]);
}

// ---------------- launch ----------------
extern "C" void kernel_launch(void* const* d_in, const int* in_sizes, int n_in,
                              void* d_out, int out_size) {
    const float* x   = (const float*)d_in[0];
    const int*   ei  = (const int*)d_in[1];      // edge_index is int32 (JAX x64 disabled)
    const float* W1  = (const float*)d_in[2];
    const float* a1s = (const float*)d_in[3];
    const float* a1d = (const float*)d_in[4];
    const float* b1  = (const float*)d_in[5];
    const float* W2  = (const float*)d_in[6];
    const float* a2s = (const float*)d_in[7];
    const float* a2d = (const float*)d_in[8];
    const float* b2  = (const float*)d_in[9];
    float*       out = (float*)d_out;

    // CSR build
    k_init<<<(NN + 255) / 256, 256>>>();
    k_count<<<(TOT + 255) / 256, 256>>>(ei);
    k_scan<<<1, 1024>>>();
    k_scatter<<<(TOT + 255) / 256, 256>>>(ei);

    // layer 1
    k_gemm1<<<dim3((NN + 127) / 128, HC / 64), 256>>>(x, W1);
    k_alpha1<<<(NN * HEADS + 255) / 256, 256>>>(a1s, a1d);
    k_agg1<<<NN, 256>>>(b1);

    // layer 2
    k_gemm2<<<(NN + 127) / 128, 320>>>(W2);
    k_alpha2<<<(NN + 255) / 256, 256>>>(a2s, a2d);
    k_agg2<<<NN, 64>>>(b2, out);
}

// round 7
// speedup vs baseline: 1.2467x; 1.0482x over previous
#include <cuda_runtime.h>
#include <math.h>

#define NN 20000
#define FEAT 128
#define HID 32
#define HEADS 8
#define HC 256          // HEADS*HID
#define CLS 40
#define E_IN 640000
#define TOT (E_IN + NN)
#define NEG 0.2f

// ---------------- scratch (device globals; no allocation allowed) ----------------
__device__ float g_h1[NN * HC];       // layer1 linear output
__device__ float g_h2[NN * HC];       // layer1 GAT output after ELU
__device__ float g_as1[NN * HEADS];
__device__ float g_ad1[NN * HEADS];
__device__ float g_g2[NN * CLS];      // layer2 linear output
__device__ float g_as2[NN];
__device__ float g_ad2[NN];
__device__ int   g_rowptr[NN + 1];
__device__ int   g_cnt[NN];
__device__ int   g_cur[NN];
__device__ int   g_esrc[TOT];         // src node per CSR slot (sorted by dst)

// ---------------- helpers (edge_index is INT32; loads always in-bounds) ----------------
__device__ __forceinline__ int edge_src(const int* ei, int e) {
    int idx = (e < E_IN) ? e : 0;
    int v = ei[idx];
    return (e < E_IN) ? v : (e - E_IN);
}
__device__ __forceinline__ int edge_dst(const int* ei, int e) {
    int idx = (e < E_IN) ? (E_IN + e) : 0;
    int v = ei[idx];
    return (e < E_IN) ? v : (e - E_IN);
}
__device__ __forceinline__ float lrelu(float v) { return v > 0.0f ? v : NEG * v; }

// ---------------- init ----------------
__global__ void k_init() {
    int t = blockIdx.x * blockDim.x + threadIdx.x;
    if (t < NN) g_cnt[t] = 0;
}

// ---------------- CSR build (int atomics only) ----------------
__global__ void k_count(const int* __restrict__ ei) {
    int t = blockIdx.x * blockDim.x + threadIdx.x;
    if (t >= TOT) return;
    atomicAdd(&g_cnt[edge_dst(ei, t)], 1);
}

// Chunked exclusive scan: thread t owns elements [t*CH, t*CH+CH).
__global__ void k_scan() {
    const int CH = (NN + 1023) / 1024;            // 20
    __shared__ int sm[1024];
    int tid = threadIdx.x;
    int base = tid * CH;

    int sum = 0;
    for (int j = 0; j < CH; j++) {
        int i = base + j;
        int idx = (i < NN) ? i : 0;
        int v = g_cnt[idx];
        if (i >= NN) v = 0;
        sum += v;
    }
    sm[tid] = sum;
    __syncthreads();

    for (int off = 1; off < 1024; off <<= 1) {
        int idx = (tid >= off) ? (tid - off) : tid;   // always valid
        int t2 = sm[idx];
        if (tid < off) t2 = 0;
        __syncthreads();
        sm[tid] += t2;
        __syncthreads();
    }

    int run = sm[tid] - sum;                      // exclusive prefix of this chunk
    for (int j = 0; j < CH; j++) {
        int i = base + j;
        if (i < NN) {
            g_rowptr[i] = run;
            g_cur[i] = run;
            run += g_cnt[i];
        }
    }
    if (tid == 1023) g_rowptr[NN] = sm[1023];
}

__global__ void k_scatter(const int* __restrict__ ei) {
    int t = blockIdx.x * blockDim.x + threadIdx.x;
    if (t >= TOT) return;
    int d = edge_dst(ei, t);
    int s = edge_src(ei, t);
    int pos = atomicAdd(&g_cur[d], 1);
    g_esrc[pos] = s;
}

// ---------------- GEMM1: x[NN,FEAT] @ W1[FEAT,HC] -> g_h1 ----------------
// 128x64 tile, BK=16, 256 threads, 8x4 per-thread microtile, float4 loads.
__global__ __launch_bounds__(256) void k_gemm1(const float* __restrict__ A,
                                               const float* __restrict__ B) {
    const int BM = 128, BN = 64, BK = 16;
    __shared__ __align__(16) float As[BK][BM];   // transposed: As[k][m]
    __shared__ __align__(16) float Bs[BK][BN];
    int tid = threadIdx.x;
    int tn = tid & 15;          // 0..15 : column group (4 cols)
    int tm = tid >> 4;          // 0..15 : row group (8 rows)
    int row0 = blockIdx.x * BM;
    int col0 = blockIdx.y * BN;
    float acc[8][4] = {};

    for (int k0 = 0; k0 < FEAT; k0 += BK) {
#pragma unroll
        for (int j = 0; j < 2; j++) {
            int li = tid * 2 + j;           // 0..511
            int r = li >> 2;                // 0..127
            int c4 = li & 3;                // 0..3
            int gr = row0 + r;
            if (gr > NN - 1) gr = NN - 1;   // clamp: OOB rows guarded at store
            float4 v = *(const float4*)&A[gr * FEAT + k0 + c4 * 4];
            As[c4 * 4 + 0][r] = v.x;
            As[c4 * 4 + 1][r] = v.y;
            As[c4 * 4 + 2][r] = v.z;
            As[c4 * 4 + 3][r] = v.w;
        }
        {
            int r = tid >> 4;               // 0..15
            int c4 = tid & 15;              // 0..15
            *(float4*)&Bs[r][c4 * 4] = *(const float4*)&B[(k0 + r) * HC + col0 + c4 * 4];
        }
        __syncthreads();
#pragma unroll
        for (int k = 0; k < BK; k++) {
            float a[8], b[4];
            *(float4*)&a[0] = *(const float4*)&As[k][tm * 8];
            *(float4*)&a[4] = *(const float4*)&As[k][tm * 8 + 4];
            *(float4*)&b[0] = *(const float4*)&Bs[k][tn * 4];
#pragma unroll
            for (int i = 0; i < 8; i++)
#pragma unroll
                for (int j = 0; j < 4; j++)
                    acc[i][j] += a[i] * b[j];
        }
        __syncthreads();
    }
#pragma unroll
    for (int i = 0; i < 8; i++) {
        int gr = row0 + tm * 8 + i;
        if (gr < NN)
            *(float4*)&g_h1[gr * HC + col0 + tn * 4] =
                make_float4(acc[i][0], acc[i][1], acc[i][2], acc[i][3]);
    }
}

// ---------------- GEMM2: g_h2[NN,HC] @ W2[HC,CLS] -> g_g2 ----------------
__global__ __launch_bounds__(320) void k_gemm2(const float* __restrict__ B) {
    const int BM = 128, BN = 40, BK = 16, NT = 320;
    __shared__ __align__(16) float As[BK][BM];   // transposed
    __shared__ __align__(16) float Bs[BK][BN];
    int tid = threadIdx.x;
    int tn = tid % 10;          // 0..9  : column group (4 cols)
    int tm = tid / 10;          // 0..31 : row group (4 rows)
    int row0 = blockIdx.x * BM;
    float acc[4][4] = {};

    for (int k0 = 0; k0 < HC; k0 += BK) {
        for (int li = tid; li < 512; li += NT) {
            int r = li >> 2;
            int c4 = li & 3;
            int gr = row0 + r;
            if (gr > NN - 1) gr = NN - 1;
            float4 v = *(const float4*)&g_h2[gr * HC + k0 + c4 * 4];
            As[c4 * 4 + 0][r] = v.x;
            As[c4 * 4 + 1][r] = v.y;
            As[c4 * 4 + 2][r] = v.z;
            As[c4 * 4 + 3][r] = v.w;
        }
        for (int li = tid; li < 160; li += NT) {
            int r = li / 10;
            int c4 = li % 10;
            *(float4*)&Bs[r][c4 * 4] = *(const float4*)&B[(k0 + r) * CLS + c4 * 4];
        }
        __syncthreads();
#pragma unroll
        for (int k = 0; k < BK; k++) {
            float a[4], b[4];
            *(float4*)&a[0] = *(const float4*)&As[k][tm * 4];
            *(float4*)&b[0] = *(const float4*)&Bs[k][tn * 4];
#pragma unroll
            for (int i = 0; i < 4; i++)
#pragma unroll
                for (int j = 0; j < 4; j++)
                    acc[i][j] += a[i] * b[j];
        }
        __syncthreads();
    }
#pragma unroll
    for (int i = 0; i < 4; i++) {
        int gr = row0 + tm * 4 + i;
        if (gr < NN)
            *(float4*)&g_g2[gr * CLS + tn * 4] =
                make_float4(acc[i][0], acc[i][1], acc[i][2], acc[i][3]);
    }
}

// ---------------- layer1 alpha projections ----------------
__global__ void k_alpha1(const float* __restrict__ a1s, const float* __restrict__ a1d) {
    int t = blockIdx.x * blockDim.x + threadIdx.x;
    if (t >= NN * HEADS) return;
    int n = t >> 3, h = t & 7;
    const float* hp = &g_h1[n * HC + h * HID];
    const float* ap = &a1s[h * HID];
    const float* dp = &a1d[h * HID];
    float accS = 0.0f, accD = 0.0f;
#pragma unroll
    for (int c = 0; c < HID; c++) {
        float hv = hp[c];
        accS += hv * ap[c];
        accD += hv * dp[c];
    }
    g_as1[t] = accS;
    g_ad1[t] = accD;
}

// ---------------- layer1: online softmax + aggregation + bias + ELU (single pass) ----------------
// One block per dst node; warp h handles head h (8 warps = 256 threads).
__global__ void k_agg1(const float* __restrict__ b1) {
    int n = blockIdx.x;
    int h = threadIdx.x >> 5;
    int lane = threadIdx.x & 31;
    int beg = g_rowptr[n], end = g_rowptr[n + 1];
    float ad = g_ad1[n * HEADS + h];

    float m = -INFINITY, ssum = 0.0f, acc = 0.0f;
    for (int i0 = beg; i0 < end; i0 += 32) {
        int i = i0 + lane;
        int sl = 0;
        float e = -INFINITY;
        if (i < end) {
            sl = g_esrc[i];
            e = lrelu(g_as1[sl * HEADS + h] + ad);
        }
        // chunk max
        float cm = e;
#pragma unroll
        for (int o = 16; o; o >>= 1) cm = fmaxf(cm, __shfl_xor_sync(0xffffffffu, cm, o));
        float mn = fmaxf(m, cm);
        float scale = __expf(m - mn);       // first chunk: exp(-inf - finite) = 0
        acc *= scale;
        ssum *= scale;
        m = mn;
        float w = (i < end) ? __expf(e - mn) : 0.0f;
        float ws = w;
#pragma unroll
        for (int o = 16; o; o >>= 1) ws += __shfl_xor_sync(0xffffffffu, ws, o);
        ssum += ws;
        // gather: broadcast (w, src) lane-by-lane; lane = channel within head
        int lim = min(32, end - i0);
        for (int j = 0; j < lim; j++) {
            float wj = __shfl_sync(0xffffffffu, w, j);
            int   s2 = __shfl_sync(0xffffffffu, sl, j);
            acc += wj * g_h1[s2 * HC + h * HID + lane];
        }
    }
    float o = acc / ssum + b1[h * HID + lane];
    g_h2[n * HC + h * HID + lane] = (o > 0.0f) ? o : (__expf(o) - 1.0f);   // ELU
}

// ---------------- layer2 alpha projections ----------------
__global__ void k_alpha2(const float* __restrict__ a2s, const float* __restrict__ a2d) {
    int n = blockIdx.x * blockDim.x + threadIdx.x;
    if (n >= NN) return;
    const float* gp = &g_g2[n * CLS];
    float accS = 0.0f, accD = 0.0f;
#pragma unroll
    for (int c = 0; c < CLS; c++) {
        float gv = gp[c];
        accS += gv * a2s[c];
        accD += gv * a2d[c];
    }
    g_as2[n] = accS;
    g_ad2[n] = accD;
}

// ---------------- layer2: online softmax + aggregation + bias + log_softmax ----------------
// One block (64 threads) per dst node; single pass over edges.
__global__ void k_agg2(const float* __restrict__ b2, float* __restrict__ out) {
    int n = blockIdx.x;
    int t = threadIdx.x;
    __shared__ float red[64];
    __shared__ int   s_src[64];
    __shared__ float s_w[64];
    int beg = g_rowptr[n], end = g_rowptr[n + 1];
    float ad = g_ad2[n];

    float m = -INFINITY, ssum = 0.0f, acc = 0.0f;
    for (int i0 = beg; i0 < end; i0 += 64) {
        int i = i0 + t;
        int s = 0;
        float e = -INFINITY;
        if (i < end) {
            s = g_esrc[i];
            e = lrelu(g_as2[s] + ad);
        }
        // block max of e
        red[t] = e; __syncthreads();
        for (int off = 32; off; off >>= 1) { if (t < off) red[t] = fmaxf(red[t], red[t + off]); __syncthreads(); }
        float mn = fmaxf(m, red[0]);
        __syncthreads();
        float scale = __expf(m - mn);
        acc *= scale;
        ssum *= scale;
        m = mn;
        float w = (i < end) ? __expf(e - mn) : 0.0f;
        s_src[t] = s;
        s_w[t] = w;
        red[t] = w; __syncthreads();
        for (int off = 32; off; off >>= 1) { if (t < off) red[t] += red[t + off]; __syncthreads(); }
        ssum += red[0];
        __syncthreads();
        int lim = min(64, end - i0);
        if (t < CLS)
            for (int j = 0; j < lim; j++)
                acc += s_w[j] * g_g2[s_src[j] * CLS + t];
        __syncthreads();
    }

    float o = (t < CLS) ? (acc / ssum + b2[t]) : -INFINITY;
    red[t] = o; __syncthreads();
    for (int off = 32; off; off >>= 1) { if (t < off) red[t] = fmaxf(red[t], red[t + off]); __syncthreads(); }
    float mx = red[0]; __syncthreads();
    red[t] = (t < CLS) ? __expf(o - mx) : 0.0f;
    __syncthreads();
    for (int off = 32; off; off >>= 1) { if (t < off) red[t] += red[t + off]; __syncthreads(); }
    if (t < CLS) out[n * CLS + t] = o - mx - logf(red[0]);
}

// ---------------- launch ----------------
extern "C" void kernel_launch(void* const* d_in, const int* in_sizes, int n_in,
                              void* d_out, int out_size) {
    const float* x   = (const float*)d_in[0];
    const int*   ei  = (const int*)d_in[1];      // edge_index is int32 (JAX x64 disabled)
    const float* W1  = (const float*)d_in[2];
    const float* a1s = (const float*)d_in[3];
    const float* a1d = (const float*)d_in[4];
    const float* b1  = (const float*)d_in[5];
    const float* W2  = (const float*)d_in[6];
    const float* a2s = (const float*)d_in[7];
    const float* a2d = (const float*)d_in[8];
    const float* b2  = (const float*)d_in[9];
    float*       out = (float*)d_out;

    // CSR build
    k_init<<<(NN + 255) / 256, 256>>>();
    k_count<<<(TOT + 255) / 256, 256>>>(ei);
    k_scan<<<1, 1024>>>();
    k_scatter<<<(TOT + 255) / 256, 256>>>(ei);

    // layer 1
    k_gemm1<<<dim3((NN + 127) / 128, HC / 64), 256>>>(x, W1);
    k_alpha1<<<(NN * HEADS + 255) / 256, 256>>>(a1s, a1d);
    k_agg1<<<NN, 256>>>(b1);

    // layer 2
    k_gemm2<<<(NN + 127) / 128, 320>>>(W2);
    k_alpha2<<<(NN + 255) / 256, 256>>>(a2s, a2d);
    k_agg2<<<NN, 64>>>(b2, out);
}

// round 8
// speedup vs baseline: 1.4304x; 1.1474x over previous
#include <cuda_runtime.h>
#include <cuda_fp16.h>
#include <math.h>

#define NN 20000
#define FEAT 128
#define HID 32
#define HEADS 8
#define HC 256          // HEADS*HID
#define CLS 40
#define E_IN 640000
#define TOT (E_IN + NN)
#define NEG 0.2f

// ---------------- scratch (device globals; no allocation allowed) ----------------
__device__ float  g_h1[NN * HC];       // layer1 linear output (fp32, for alpha proj)
__device__ __half g_h1h[NN * HC];      // layer1 linear output (fp16, for gather)
__device__ float  g_h2[NN * HC];       // layer1 GAT output after ELU
__device__ float  g_as1[NN * HEADS];
__device__ float  g_ad1[NN * HEADS];
__device__ float  g_g2[NN * CLS];      // layer2 linear output
__device__ float  g_as2[NN];
__device__ float  g_ad2[NN];
__device__ int    g_rowptr[NN + 1];
__device__ int    g_cnt[NN];
__device__ int    g_cur[NN];
__device__ int    g_esrc[TOT];         // src node per CSR slot (sorted by dst)

// ---------------- helpers (edge_index is INT32; loads always in-bounds) ----------------
__device__ __forceinline__ int edge_src(const int* ei, int e) {
    int idx = (e < E_IN) ? e : 0;
    int v = ei[idx];
    return (e < E_IN) ? v : (e - E_IN);
}
__device__ __forceinline__ int edge_dst(const int* ei, int e) {
    int idx = (e < E_IN) ? (E_IN + e) : 0;
    int v = ei[idx];
    return (e < E_IN) ? v : (e - E_IN);
}
__device__ __forceinline__ float lrelu(float v) { return v > 0.0f ? v : NEG * v; }

// ---------------- init ----------------
__global__ void k_init() {
    int t = blockIdx.x * blockDim.x + threadIdx.x;
    if (t < NN) g_cnt[t] = 0;
}

// ---------------- CSR build (int atomics only) ----------------
__global__ void k_count(const int* __restrict__ ei) {
    int t = blockIdx.x * blockDim.x + threadIdx.x;
    if (t >= TOT) return;
    atomicAdd(&g_cnt[edge_dst(ei, t)], 1);
}

// Chunked exclusive scan: thread t owns elements [t*CH, t*CH+CH).
__global__ void k_scan() {
    const int CH = (NN + 1023) / 1024;            // 20
    __shared__ int sm[1024];
    int tid = threadIdx.x;
    int base = tid * CH;

    int sum = 0;
    for (int j = 0; j < CH; j++) {
        int i = base + j;
        int idx = (i < NN) ? i : 0;
        int v = g_cnt[idx];
        if (i >= NN) v = 0;
        sum += v;
    }
    sm[tid] = sum;
    __syncthreads();

    for (int off = 1; off < 1024; off <<= 1) {
        int idx = (tid >= off) ? (tid - off) : tid;   // always valid
        int t2 = sm[idx];
        if (tid < off) t2 = 0;
        __syncthreads();
        sm[tid] += t2;
        __syncthreads();
    }

    int run = sm[tid] - sum;                      // exclusive prefix of this chunk
    for (int j = 0; j < CH; j++) {
        int i = base + j;
        if (i < NN) {
            g_rowptr[i] = run;
            g_cur[i] = run;
            run += g_cnt[i];
        }
    }
    if (tid == 1023) g_rowptr[NN] = sm[1023];
}

__global__ void k_scatter(const int* __restrict__ ei) {
    int t = blockIdx.x * blockDim.x + threadIdx.x;
    if (t >= TOT) return;
    int d = edge_dst(ei, t);
    int s = edge_src(ei, t);
    int pos = atomicAdd(&g_cur[d], 1);
    g_esrc[pos] = s;
}

// ---------------- GEMM1: x[NN,FEAT] @ W1[FEAT,HC] -> g_h1 (fp32 + fp16) ----------------
__global__ __launch_bounds__(256) void k_gemm1(const float* __restrict__ A,
                                               const float* __restrict__ B) {
    const int BM = 128, BN = 64, BK = 16;
    __shared__ __align__(16) float As[BK][BM];   // transposed: As[k][m]
    __shared__ __align__(16) float Bs[BK][BN];
    int tid = threadIdx.x;
    int tn = tid & 15;          // 0..15 : column group (4 cols)
    int tm = tid >> 4;          // 0..15 : row group (8 rows)
    int row0 = blockIdx.x * BM;
    int col0 = blockIdx.y * BN;
    float acc[8][4] = {};

    for (int k0 = 0; k0 < FEAT; k0 += BK) {
#pragma unroll
        for (int j = 0; j < 2; j++) {
            int li = tid * 2 + j;           // 0..511
            int r = li >> 2;                // 0..127
            int c4 = li & 3;                // 0..3
            int gr = row0 + r;
            if (gr > NN - 1) gr = NN - 1;   // clamp: OOB rows guarded at store
            float4 v = *(const float4*)&A[gr * FEAT + k0 + c4 * 4];
            As[c4 * 4 + 0][r] = v.x;
            As[c4 * 4 + 1][r] = v.y;
            As[c4 * 4 + 2][r] = v.z;
            As[c4 * 4 + 3][r] = v.w;
        }
        {
            int r = tid >> 4;               // 0..15
            int c4 = tid & 15;              // 0..15
            *(float4*)&Bs[r][c4 * 4] = *(const float4*)&B[(k0 + r) * HC + col0 + c4 * 4];
        }
        __syncthreads();
#pragma unroll
        for (int k = 0; k < BK; k++) {
            float a[8], b[4];
            *(float4*)&a[0] = *(const float4*)&As[k][tm * 8];
            *(float4*)&a[4] = *(const float4*)&As[k][tm * 8 + 4];
            *(float4*)&b[0] = *(const float4*)&Bs[k][tn * 4];
#pragma unroll
            for (int i = 0; i < 8; i++)
#pragma unroll
                for (int j = 0; j < 4; j++)
                    acc[i][j] += a[i] * b[j];
        }
        __syncthreads();
    }
#pragma unroll
    for (int i = 0; i < 8; i++) {
        int gr = row0 + tm * 8 + i;
        if (gr < NN) {
            int c = col0 + tn * 4;
            *(float4*)&g_h1[gr * HC + c] =
                make_float4(acc[i][0], acc[i][1], acc[i][2], acc[i][3]);
            __half2* hp = (__half2*)&g_h1h[gr * HC + c];
            hp[0] = __float22half2_rn(make_float2(acc[i][0], acc[i][1]));
            hp[1] = __float22half2_rn(make_float2(acc[i][2], acc[i][3]));
        }
    }
}

// ---------------- GEMM2: g_h2[NN,HC] @ W2[HC,CLS] -> g_g2 ----------------
__global__ __launch_bounds__(320) void k_gemm2(const float* __restrict__ B) {
    const int BM = 128, BN = 40, BK = 16, NT = 320;
    __shared__ __align__(16) float As[BK][BM];   // transposed
    __shared__ __align__(16) float Bs[BK][BN];
    int tid = threadIdx.x;
    int tn = tid % 10;          // 0..9  : column group (4 cols)
    int tm = tid / 10;          // 0..31 : row group (4 rows)
    int row0 = blockIdx.x * BM;
    float acc[4][4] = {};

    for (int k0 = 0; k0 < HC; k0 += BK) {
        for (int li = tid; li < 512; li += NT) {
            int r = li >> 2;
            int c4 = li & 3;
            int gr = row0 + r;
            if (gr > NN - 1) gr = NN - 1;
            float4 v = *(const float4*)&g_h2[gr * HC + k0 + c4 * 4];
            As[c4 * 4 + 0][r] = v.x;
            As[c4 * 4 + 1][r] = v.y;
            As[c4 * 4 + 2][r] = v.z;
            As[c4 * 4 + 3][r] = v.w;
        }
        for (int li = tid; li < 160; li += NT) {
            int r = li / 10;
            int c4 = li % 10;
            *(float4*)&Bs[r][c4 * 4] = *(const float4*)&B[(k0 + r) * CLS + c4 * 4];
        }
        __syncthreads();
#pragma unroll
        for (int k = 0; k < BK; k++) {
            float a[4], b[4];
            *(float4*)&a[0] = *(const float4*)&As[k][tm * 4];
            *(float4*)&b[0] = *(const float4*)&Bs[k][tn * 4];
#pragma unroll
            for (int i = 0; i < 4; i++)
#pragma unroll
                for (int j = 0; j < 4; j++)
                    acc[i][j] += a[i] * b[j];
        }
        __syncthreads();
    }
#pragma unroll
    for (int i = 0; i < 4; i++) {
        int gr = row0 + tm * 4 + i;
        if (gr < NN)
            *(float4*)&g_g2[gr * CLS + tn * 4] =
                make_float4(acc[i][0], acc[i][1], acc[i][2], acc[i][3]);
    }
}

// ---------------- layer1 alpha projections ----------------
__global__ void k_alpha1(const float* __restrict__ a1s, const float* __restrict__ a1d) {
    int t = blockIdx.x * blockDim.x + threadIdx.x;
    if (t >= NN * HEADS) return;
    int n = t >> 3, h = t & 7;
    const float* hp = &g_h1[n * HC + h * HID];
    const float* ap = &a1s[h * HID];
    const float* dp = &a1d[h * HID];
    float accS = 0.0f, accD = 0.0f;
#pragma unroll
    for (int c = 0; c < HID; c++) {
        float hv = hp[c];
        accS += hv * ap[c];
        accD += hv * dp[c];
    }
    g_as1[t] = accS;
    g_ad1[t] = accD;
}

// ---------------- layer1: online softmax + fp16 gather + bias + ELU ----------------
// 128 threads per dst node; warp wp covers heads 2wp, 2wp+1 (64 channels = 32 half2).
// Lanes 0-15 compute edge weights for head 2wp, lanes 16-31 for head 2wp+1 (same edges).
__global__ __launch_bounds__(128) void k_agg1(const float* __restrict__ b1) {
    int n = blockIdx.x;
    int wp = threadIdx.x >> 5;          // 0..3
    int lane = threadIdx.x & 31;
    int hl = lane >> 4;                 // head within pair
    int h = wp * 2 + hl;
    int el = lane & 15;                 // edge slot within 16-edge chunk
    int beg = g_rowptr[n], end = g_rowptr[n + 1];
    float ad = g_ad1[n * HEADS + h];
    const __half2* __restrict__ h1h2 = (const __half2*)g_h1h;

    float m = -INFINITY, ssum = 0.0f;
    float2 acc = make_float2(0.0f, 0.0f);
    for (int i0 = beg; i0 < end; i0 += 16) {
        int i = i0 + el;
        int sl = 0;
        float e = -INFINITY;
        if (i < end) {
            sl = g_esrc[i];
            e = lrelu(g_as1[sl * HEADS + h] + ad);
        }
        // half-warp max (offsets < 16 keep the two halves separate)
        float cm = e;
#pragma unroll
        for (int o = 8; o; o >>= 1) cm = fmaxf(cm, __shfl_xor_sync(0xffffffffu, cm, o));
        float mn = fmaxf(m, cm);
        float sc = __expf(m - mn);
        acc.x *= sc; acc.y *= sc; ssum *= sc;
        m = mn;
        float w = (i < end) ? __expf(e - mn) : 0.0f;
        float ws = w;
#pragma unroll
        for (int o = 8; o; o >>= 1) ws += __shfl_xor_sync(0xffffffffu, ws, o);
        ssum += ws;
        // gather: per edge, full warp loads 32 half2 = 128B contiguous (2 heads)
        int lim = min(16, end - i0);
        for (int j = 0; j < lim; j++) {
            int   s2 = __shfl_sync(0xffffffffu, sl, j);
            float wj = __shfl_sync(0xffffffffu, w, j + (hl << 4));
            float2 v = __half22float2(h1h2[s2 * (HC / 2) + wp * 32 + lane]);
            acc.x += wj * v.x;
            acc.y += wj * v.y;
        }
    }
    int c0 = wp * 64 + lane * 2;
    float inv_s = 1.0f / ssum;
    float o0 = acc.x * inv_s + b1[c0];
    float o1 = acc.y * inv_s + b1[c0 + 1];
    g_h2[n * HC + c0]     = (o0 > 0.0f) ? o0 : (__expf(o0) - 1.0f);
    g_h2[n * HC + c0 + 1] = (o1 > 0.0f) ? o1 : (__expf(o1) - 1.0f);
}

// ---------------- layer2 alpha projections ----------------
__global__ void k_alpha2(const float* __restrict__ a2s, const float* __restrict__ a2d) {
    int n = blockIdx.x * blockDim.x + threadIdx.x;
    if (n >= NN) return;
    const float* gp = &g_g2[n * CLS];
    float accS = 0.0f, accD = 0.0f;
#pragma unroll
    for (int c = 0; c < CLS; c++) {
        float gv = gp[c];
        accS += gv * a2s[c];
        accD += gv * a2d[c];
    }
    g_as2[n] = accS;
    g_ad2[n] = accD;
}

// ---------------- layer2: online softmax + aggregation + bias + log_softmax ----------------
__global__ void k_agg2(const float* __restrict__ b2, float* __restrict__ out) {
    int n = blockIdx.x;
    int t = threadIdx.x;
    __shared__ float red[64];
    __shared__ int   s_src[64];
    __shared__ float s_w[64];
    int beg = g_rowptr[n], end = g_rowptr[n + 1];
    float ad = g_ad2[n];

    float m = -INFINITY, ssum = 0.0f, acc = 0.0f;
    for (int i0 = beg; i0 < end; i0 += 64) {
        int i = i0 + t;
        int s = 0;
        float e = -INFINITY;
        if (i < end) {
            s = g_esrc[i];
            e = lrelu(g_as2[s] + ad);
        }
        red[t] = e; __syncthreads();
        for (int off = 32; off; off >>= 1) { if (t < off) red[t] = fmaxf(red[t], red[t + off]); __syncthreads(); }
        float mn = fmaxf(m, red[0]);
        __syncthreads();
        float scale = __expf(m - mn);
        acc *= scale;
        ssum *= scale;
        m = mn;
        float w = (i < end) ? __expf(e - mn) : 0.0f;
        s_src[t] = s;
        s_w[t] = w;
        red[t] = w; __syncthreads();
        for (int off = 32; off; off >>= 1) { if (t < off) red[t] += red[t + off]; __syncthreads(); }
        ssum += red[0];
        __syncthreads();
        int lim = min(64, end - i0);
        if (t < CLS)
            for (int j = 0; j < lim; j++)
                acc += s_w[j] * g_g2[s_src[j] * CLS + t];
        __syncthreads();
    }

    float o = (t < CLS) ? (acc / ssum + b2[t]) : -INFINITY;
    red[t] = o; __syncthreads();
    for (int off = 32; off; off >>= 1) { if (t < off) red[t] = fmaxf(red[t], red[t + off]); __syncthreads(); }
    float mx = red[0]; __syncthreads();
    red[t] = (t < CLS) ? __expf(o - mx) : 0.0f;
    __syncthreads();
    for (int off = 32; off; off >>= 1) { if (t < off) red[t] += red[t + off]; __syncthreads(); }
    if (t < CLS) out[n * CLS + t] = o - mx - logf(red[0]);
}

// ---------------- launch ----------------
extern "C" void kernel_launch(void* const* d_in, const int* in_sizes, int n_in,
                              void* d_out, int out_size) {
    const float* x   = (const float*)d_in[0];
    const int*   ei  = (const int*)d_in[1];      // edge_index is int32 (JAX x64 disabled)
    const float* W1  = (const float*)d_in[2];
    const float* a1s = (const float*)d_in[3];
    const float* a1d = (const float*)d_in[4];
    const float* b1  = (const float*)d_in[5];
    const float* W2  = (const float*)d_in[6];
    const float* a2s = (const float*)d_in[7];
    const float* a2d = (const float*)d_in[8];
    const float* b2  = (const float*)d_in[9];
    float*       out = (float*)d_out;

    // CSR build
    k_init<<<(NN + 255) / 256, 256>>>();
    k_count<<<(TOT + 255) / 256, 256>>>(ei);
    k_scan<<<1, 1024>>>();
    k_scatter<<<(TOT + 255) / 256, 256>>>(ei);

    // layer 1
    k_gemm1<<<dim3((NN + 127) / 128, HC / 64), 256>>>(x, W1);
    k_alpha1<<<(NN * HEADS + 255) / 256, 256>>>(a1s, a1d);
    k_agg1<<<NN, 128>>>(b1);

    // layer 2
    k_gemm2<<<(NN + 127) / 128, 320>>>(W2);
    k_alpha2<<<(NN + 255) / 256, 256>>>(a2s, a2d);
    k_agg2<<<NN, 64>>>(b2, out);
}

// round 9
// speedup vs baseline: 1.6490x; 1.1528x over previous
#include <cuda_runtime.h>
#include <cuda_fp16.h>
#include <math.h>

#define NN 20000
#define FEAT 128
#define HID 32
#define HEADS 8
#define HC 256          // HEADS*HID
#define CLS 40
#define E_IN 640000
#define TOT (E_IN + NN)
#define NEG 0.2f

// ---------------- scratch (device globals; no allocation allowed) ----------------
__device__ __half g_h1h[NN * HC];      // layer1 linear output (fp16, for gather)
__device__ float  g_h2[NN * HC];       // layer1 GAT output after ELU
__device__ float  g_as1[NN * HEADS];
__device__ float  g_ad1[NN * HEADS];
__device__ float  g_g2[NN * CLS];      // layer2 linear output (fp32, for alpha2)
__device__ __half g_g2h[NN * CLS];     // layer2 linear output (fp16, for gather)
__device__ float  g_as2[NN];
__device__ float  g_ad2[NN];
__device__ int    g_rowptr[NN + 1];
__device__ int    g_cnt[NN];
__device__ int    g_cur[NN];
__device__ int    g_esrc[TOT];         // src node per CSR slot (sorted by dst)

// ---------------- helpers (edge_index is INT32; loads always in-bounds) ----------------
__device__ __forceinline__ int edge_src(const int* ei, int e) {
    int idx = (e < E_IN) ? e : 0;
    int v = ei[idx];
    return (e < E_IN) ? v : (e - E_IN);
}
__device__ __forceinline__ int edge_dst(const int* ei, int e) {
    int idx = (e < E_IN) ? (E_IN + e) : 0;
    int v = ei[idx];
    return (e < E_IN) ? v : (e - E_IN);
}
__device__ __forceinline__ float lrelu(float v) { return v > 0.0f ? v : NEG * v; }

// ---------------- init ----------------
__global__ void k_init() {
    int t = blockIdx.x * blockDim.x + threadIdx.x;
    if (t < NN) g_cnt[t] = 0;
}

// ---------------- CSR build: 4 edges/thread for atomic MLP ----------------
__global__ void k_count(const int* __restrict__ ei) {
    int t = blockIdx.x * blockDim.x + threadIdx.x;
    int e0 = t * 4;
    if (e0 >= TOT) return;
    if (e0 + 3 < E_IN) {
        int4 d4 = *(const int4*)&ei[E_IN + e0];
        atomicAdd(&g_cnt[d4.x], 1);
        atomicAdd(&g_cnt[d4.y], 1);
        atomicAdd(&g_cnt[d4.z], 1);
        atomicAdd(&g_cnt[d4.w], 1);
    } else {
        for (int k = 0; k < 4 && e0 + k < TOT; k++)
            atomicAdd(&g_cnt[edge_dst(ei, e0 + k)], 1);
    }
}

// Chunked exclusive scan: thread t owns elements [t*CH, t*CH+CH).
__global__ void k_scan() {
    const int CH = (NN + 1023) / 1024;            // 20
    __shared__ int sm[1024];
    int tid = threadIdx.x;
    int base = tid * CH;

    int sum = 0;
    for (int j = 0; j < CH; j++) {
        int i = base + j;
        int idx = (i < NN) ? i : 0;
        int v = g_cnt[idx];
        if (i >= NN) v = 0;
        sum += v;
    }
    sm[tid] = sum;
    __syncthreads();

    for (int off = 1; off < 1024; off <<= 1) {
        int idx = (tid >= off) ? (tid - off) : tid;   // always valid
        int t2 = sm[idx];
        if (tid < off) t2 = 0;
        __syncthreads();
        sm[tid] += t2;
        __syncthreads();
    }

    int run = sm[tid] - sum;                      // exclusive prefix of this chunk
    for (int j = 0; j < CH; j++) {
        int i = base + j;
        if (i < NN) {
            g_rowptr[i] = run;
            g_cur[i] = run;
            run += g_cnt[i];
        }
    }
    if (tid == 1023) g_rowptr[NN] = sm[1023];
}

__global__ void k_scatter(const int* __restrict__ ei) {
    int t = blockIdx.x * blockDim.x + threadIdx.x;
    int e0 = t * 4;
    if (e0 >= TOT) return;
    if (e0 + 3 < E_IN) {
        int4 s4 = *(const int4*)&ei[e0];
        int4 d4 = *(const int4*)&ei[E_IN + e0];
        int p0 = atomicAdd(&g_cur[d4.x], 1);
        int p1 = atomicAdd(&g_cur[d4.y], 1);
        int p2 = atomicAdd(&g_cur[d4.z], 1);
        int p3 = atomicAdd(&g_cur[d4.w], 1);
        g_esrc[p0] = s4.x;
        g_esrc[p1] = s4.y;
        g_esrc[p2] = s4.z;
        g_esrc[p3] = s4.w;
    } else {
        for (int k = 0; k < 4 && e0 + k < TOT; k++) {
            int e = e0 + k;
            int d = edge_dst(ei, e);
            int s = edge_src(ei, e);
            int pos = atomicAdd(&g_cur[d], 1);
            g_esrc[pos] = s;
        }
    }
}

// ---------------- GEMM1: x @ W1 -> g_h1h (fp16) + fused alpha1 projections ----------------
// 128x64 tile (block covers 2 full heads), BK=16, 256 threads, 8x4 microtile.
__global__ __launch_bounds__(256) void k_gemm1(const float* __restrict__ A,
                                               const float* __restrict__ B,
                                               const float* __restrict__ a1s,
                                               const float* __restrict__ a1d) {
    const int BM = 128, BN = 64, BK = 16;
    __shared__ __align__(16) float As[BK][BM];   // transposed: As[k][m]
    __shared__ __align__(16) float Bs[BK][BN];
    int tid = threadIdx.x;
    int tn = tid & 15;          // 0..15 : column group (4 cols)
    int tm = tid >> 4;          // 0..15 : row group (8 rows)
    int lane = tid & 31;
    int row0 = blockIdx.x * BM;
    int col0 = blockIdx.y * BN;
    float acc[8][4] = {};

    for (int k0 = 0; k0 < FEAT; k0 += BK) {
#pragma unroll
        for (int j = 0; j < 2; j++) {
            int li = tid * 2 + j;           // 0..511
            int r = li >> 2;                // 0..127
            int c4 = li & 3;                // 0..3
            int gr = row0 + r;
            if (gr > NN - 1) gr = NN - 1;   // clamp: OOB rows guarded at store
            float4 v = *(const float4*)&A[gr * FEAT + k0 + c4 * 4];
            As[c4 * 4 + 0][r] = v.x;
            As[c4 * 4 + 1][r] = v.y;
            As[c4 * 4 + 2][r] = v.z;
            As[c4 * 4 + 3][r] = v.w;
        }
        {
            int r = tid >> 4;               // 0..15
            int c4 = tid & 15;              // 0..15
            *(float4*)&Bs[r][c4 * 4] = *(const float4*)&B[(k0 + r) * HC + col0 + c4 * 4];
        }
        __syncthreads();
#pragma unroll
        for (int k = 0; k < BK; k++) {
            float a[8], b[4];
            *(float4*)&a[0] = *(const float4*)&As[k][tm * 8];
            *(float4*)&a[4] = *(const float4*)&As[k][tm * 8 + 4];
            *(float4*)&b[0] = *(const float4*)&Bs[k][tn * 4];
#pragma unroll
            for (int i = 0; i < 8; i++)
#pragma unroll
                for (int j = 0; j < 4; j++)
                    acc[i][j] += a[i] * b[j];
        }
        __syncthreads();
    }

    // store fp16 h1
#pragma unroll
    for (int i = 0; i < 8; i++) {
        int gr = row0 + tm * 8 + i;
        if (gr < NN) {
            __half2* hp = (__half2*)&g_h1h[gr * HC + col0 + tn * 4];
            hp[0] = __float22half2_rn(make_float2(acc[i][0], acc[i][1]));
            hp[1] = __float22half2_rn(make_float2(acc[i][2], acc[i][3]));
        }
    }

    // fused alpha projections: block covers heads (blockIdx.y*2 + (tn>>3)) fully.
    int h = blockIdx.y * 2 + (tn >> 3);
    int cseg = (tn & 7) * 4;                // offset within head
    float avs[4], avd[4];
#pragma unroll
    for (int j = 0; j < 4; j++) {
        avs[j] = a1s[h * HID + cseg + j];
        avd[j] = a1d[h * HID + cseg + j];
    }
#pragma unroll
    for (int i = 0; i < 8; i++) {
        float ps = acc[i][0] * avs[0] + acc[i][1] * avs[1] + acc[i][2] * avs[2] + acc[i][3] * avs[3];
        float pd = acc[i][0] * avd[0] + acc[i][1] * avd[1] + acc[i][2] * avd[2] + acc[i][3] * avd[3];
#pragma unroll
        for (int o = 1; o <= 4; o <<= 1) {
            ps += __shfl_xor_sync(0xffffffffu, ps, o);
            pd += __shfl_xor_sync(0xffffffffu, pd, o);
        }
        int gr = row0 + tm * 8 + i;
        if ((lane & 7) == 0 && gr < NN) {
            g_as1[gr * HEADS + h] = ps;
            g_ad1[gr * HEADS + h] = pd;
        }
    }
}

// ---------------- GEMM2: g_h2 @ W2 -> g_g2 (fp32) + g_g2h (fp16) ----------------
__global__ __launch_bounds__(320) void k_gemm2(const float* __restrict__ B) {
    const int BM = 128, BN = 40, BK = 16, NT = 320;
    __shared__ __align__(16) float As[BK][BM];   // transposed
    __shared__ __align__(16) float Bs[BK][BN];
    int tid = threadIdx.x;
    int tn = tid % 10;          // 0..9  : column group (4 cols)
    int tm = tid / 10;          // 0..31 : row group (4 rows)
    int row0 = blockIdx.x * BM;
    float acc[4][4] = {};

    for (int k0 = 0; k0 < HC; k0 += BK) {
        for (int li = tid; li < 512; li += NT) {
            int r = li >> 2;
            int c4 = li & 3;
            int gr = row0 + r;
            if (gr > NN - 1) gr = NN - 1;
            float4 v = *(const float4*)&g_h2[gr * HC + k0 + c4 * 4];
            As[c4 * 4 + 0][r] = v.x;
            As[c4 * 4 + 1][r] = v.y;
            As[c4 * 4 + 2][r] = v.z;
            As[c4 * 4 + 3][r] = v.w;
        }
        for (int li = tid; li < 160; li += NT) {
            int r = li / 10;
            int c4 = li % 10;
            *(float4*)&Bs[r][c4 * 4] = *(const float4*)&B[(k0 + r) * CLS + c4 * 4];
        }
        __syncthreads();
#pragma unroll
        for (int k = 0; k < BK; k++) {
            float a[4], b[4];
            *(float4*)&a[0] = *(const float4*)&As[k][tm * 4];
            *(float4*)&b[0] = *(const float4*)&Bs[k][tn * 4];
#pragma unroll
            for (int i = 0; i < 4; i++)
#pragma unroll
                for (int j = 0; j < 4; j++)
                    acc[i][j] += a[i] * b[j];
        }
        __syncthreads();
    }
#pragma unroll
    for (int i = 0; i < 4; i++) {
        int gr = row0 + tm * 4 + i;
        if (gr < NN) {
            *(float4*)&g_g2[gr * CLS + tn * 4] =
                make_float4(acc[i][0], acc[i][1], acc[i][2], acc[i][3]);
            __half2* hp = (__half2*)&g_g2h[gr * CLS + tn * 4];
            hp[0] = __float22half2_rn(make_float2(acc[i][0], acc[i][1]));
            hp[1] = __float22half2_rn(make_float2(acc[i][2], acc[i][3]));
        }
    }
}

// ---------------- layer1: online softmax + fp16 gather + bias + ELU ----------------
// 128 threads per dst node; warp wp covers heads 2wp, 2wp+1 (64 channels = 32 half2).
__global__ __launch_bounds__(128) void k_agg1(const float* __restrict__ b1) {
    int n = blockIdx.x;
    int wp = threadIdx.x >> 5;          // 0..3
    int lane = threadIdx.x & 31;
    int hl = lane >> 4;                 // head within pair
    int h = wp * 2 + hl;
    int el = lane & 15;                 // edge slot within 16-edge chunk
    int beg = g_rowptr[n], end = g_rowptr[n + 1];
    float ad = g_ad1[n * HEADS + h];
    const __half2* __restrict__ h1h2 = (const __half2*)g_h1h;

    float m = -INFINITY, ssum = 0.0f;
    float2 acc = make_float2(0.0f, 0.0f);
    for (int i0 = beg; i0 < end; i0 += 16) {
        int i = i0 + el;
        int sl = 0;
        float e = -INFINITY;
        if (i < end) {
            sl = g_esrc[i];
            e = lrelu(g_as1[sl * HEADS + h] + ad);
        }
        float cm = e;
#pragma unroll
        for (int o = 8; o; o >>= 1) cm = fmaxf(cm, __shfl_xor_sync(0xffffffffu, cm, o));
        float mn = fmaxf(m, cm);
        float sc = __expf(m - mn);
        acc.x *= sc; acc.y *= sc; ssum *= sc;
        m = mn;
        float w = (i < end) ? __expf(e - mn) : 0.0f;
        float ws = w;
#pragma unroll
        for (int o = 8; o; o >>= 1) ws += __shfl_xor_sync(0xffffffffu, ws, o);
        ssum += ws;
        int lim = min(16, end - i0);
        for (int j = 0; j < lim; j++) {
            int   s2 = __shfl_sync(0xffffffffu, sl, j);
            float wj = __shfl_sync(0xffffffffu, w, j + (hl << 4));
            float2 v = __half22float2(h1h2[s2 * (HC / 2) + wp * 32 + lane]);
            acc.x += wj * v.x;
            acc.y += wj * v.y;
        }
    }
    int c0 = wp * 64 + lane * 2;
    float inv_s = 1.0f / ssum;
    float o0 = acc.x * inv_s + b1[c0];
    float o1 = acc.y * inv_s + b1[c0 + 1];
    g_h2[n * HC + c0]     = (o0 > 0.0f) ? o0 : (__expf(o0) - 1.0f);
    g_h2[n * HC + c0 + 1] = (o1 > 0.0f) ? o1 : (__expf(o1) - 1.0f);
}

// ---------------- layer2 alpha projections (from fp32 g_g2) ----------------
__global__ void k_alpha2(const float* __restrict__ a2s, const float* __restrict__ a2d) {
    int n = blockIdx.x * blockDim.x + threadIdx.x;
    if (n >= NN) return;
    const float* gp = &g_g2[n * CLS];
    float accS = 0.0f, accD = 0.0f;
#pragma unroll
    for (int c = 0; c < CLS; c++) {
        float gv = gp[c];
        accS += gv * a2s[c];
        accD += gv * a2d[c];
    }
    g_as2[n] = accS;
    g_ad2[n] = accD;
}

// ---------------- layer2: online softmax + fp16 gather + bias + log_softmax ----------------
// 64 threads per dst node; gather by threads 0..19 as half2 (40 channels).
__global__ void k_agg2(const float* __restrict__ b2, float* __restrict__ out) {
    int n = blockIdx.x;
    int t = threadIdx.x;
    __shared__ float red[64];
    __shared__ int   s_src[64];
    __shared__ float s_w[64];
    __shared__ float o40[CLS];
    int beg = g_rowptr[n], end = g_rowptr[n + 1];
    float ad = g_ad2[n];
    const __half2* __restrict__ g2h2 = (const __half2*)g_g2h;

    float m = -INFINITY, ssum = 0.0f;
    float2 acc = make_float2(0.0f, 0.0f);
    for (int i0 = beg; i0 < end; i0 += 64) {
        int i = i0 + t;
        int s = 0;
        float e = -INFINITY;
        if (i < end) {
            s = g_esrc[i];
            e = lrelu(g_as2[s] + ad);
        }
        red[t] = e; __syncthreads();
        for (int off = 32; off; off >>= 1) { if (t < off) red[t] = fmaxf(red[t], red[t + off]); __syncthreads(); }
        float mn = fmaxf(m, red[0]);
        __syncthreads();
        float scale = __expf(m - mn);
        acc.x *= scale; acc.y *= scale;
        ssum *= scale;
        m = mn;
        float w = (i < end) ? __expf(e - mn) : 0.0f;
        s_src[t] = s;
        s_w[t] = w;
        red[t] = w; __syncthreads();
        for (int off = 32; off; off >>= 1) { if (t < off) red[t] += red[t + off]; __syncthreads(); }
        ssum += red[0];
        __syncthreads();
        int lim = min(64, end - i0);
        if (t < CLS / 2)
            for (int j = 0; j < lim; j++) {
                float2 v = __half22float2(g2h2[s_src[j] * (CLS / 2) + t]);
                acc.x += s_w[j] * v.x;
                acc.y += s_w[j] * v.y;
            }
        __syncthreads();
    }

    if (t < CLS / 2) {
        float inv_s = 1.0f / ssum;
        o40[t * 2]     = acc.x * inv_s + b2[t * 2];
        o40[t * 2 + 1] = acc.y * inv_s + b2[t * 2 + 1];
    }
    __syncthreads();
    float o = (t < CLS) ? o40[t] : -INFINITY;
    red[t] = o; __syncthreads();
    for (int off = 32; off; off >>= 1) { if (t < off) red[t] = fmaxf(red[t], red[t + off]); __syncthreads(); }
    float mx = red[0]; __syncthreads();
    red[t] = (t < CLS) ? __expf(o - mx) : 0.0f;
    __syncthreads();
    for (int off = 32; off; off >>= 1) { if (t < off) red[t] += red[t + off]; __syncthreads(); }
    if (t < CLS) out[n * CLS + t] = o - mx - logf(red[0]);
}

// ---------------- launch ----------------
extern "C" void kernel_launch(void* const* d_in, const int* in_sizes, int n_in,
                              void* d_out, int out_size) {
    const float* x   = (const float*)d_in[0];
    const int*   ei  = (const int*)d_in[1];      // edge_index is int32 (JAX x64 disabled)
    const float* W1  = (const float*)d_in[2];
    const float* a1s = (const float*)d_in[3];
    const float* a1d = (const float*)d_in[4];
    const float* b1  = (const float*)d_in[5];
    const float* W2  = (const float*)d_in[6];
    const float* a2s = (const float*)d_in[7];
    const float* a2d = (const float*)d_in[8];
    const float* b2  = (const float*)d_in[9];
    float*       out = (float*)d_out;

    // CSR build
    k_init<<<(NN + 255) / 256, 256>>>();
    k_count<<<(TOT / 4 + 255) / 256, 256>>>(ei);
    k_scan<<<1, 1024>>>();
    k_scatter<<<(TOT / 4 + 255) / 256, 256>>>(ei);

    // layer 1
    k_gemm1<<<dim3((NN + 127) / 128, HC / 64), 256>>>(x, W1, a1s, a1d);
    k_agg1<<<NN, 128>>>(b1);

    // layer 2
    k_gemm2<<<(NN + 127) / 128, 320>>>(W2);
    k_alpha2<<<(NN + 255) / 256, 256>>>(a2s, a2d);
    k_agg2<<<NN, 64>>>(b2, out);
}

// round 10
// speedup vs baseline: 1.8011x; 1.0922x over previous
#include <cuda_runtime.h>
#include <cuda_fp16.h>
#include <mma.h>
#include <math.h>

using namespace nvcuda;

#define NN 20000
#define FEAT 128
#define HID 32
#define HEADS 8
#define HC 256          // HEADS*HID
#define CLS 40
#define E_IN 640000
#define TOT (E_IN + NN)
#define NEG 0.2f

// ---------------- scratch (device globals; no allocation allowed) ----------------
__device__ __half g_xh[NN * FEAT];     // x in fp16
__device__ __half g_w1h[FEAT * HC];    // W1 in fp16
__device__ __half g_h1h[NN * HC];      // layer1 linear output (fp16, for gather)
__device__ float  g_h2[NN * HC];       // layer1 GAT output after ELU
__device__ float  g_as1[NN * HEADS];
__device__ float  g_ad1[NN * HEADS];
__device__ float  g_g2[NN * CLS];      // layer2 linear output (fp32, for alpha2)
__device__ __half g_g2h[NN * CLS];     // layer2 linear output (fp16, for gather)
__device__ float  g_as2[NN];
__device__ float  g_ad2[NN];
__device__ int    g_rowptr[NN + 1];
__device__ int    g_cnt[NN];
__device__ int    g_cur[NN];
__device__ int    g_esrc[TOT];         // src node per CSR slot (sorted by dst)

// ---------------- helpers (edge_index is INT32; loads always in-bounds) ----------------
__device__ __forceinline__ int edge_src(const int* ei, int e) {
    int idx = (e < E_IN) ? e : 0;
    int v = ei[idx];
    return (e < E_IN) ? v : (e - E_IN);
}
__device__ __forceinline__ int edge_dst(const int* ei, int e) {
    int idx = (e < E_IN) ? (E_IN + e) : 0;
    int v = ei[idx];
    return (e < E_IN) ? v : (e - E_IN);
}
__device__ __forceinline__ float lrelu(float v) { return v > 0.0f ? v : NEG * v; }

// ---------------- init + fp16 conversion ----------------
__global__ void k_init() {
    int t = blockIdx.x * blockDim.x + threadIdx.x;
    if (t < NN) g_cnt[t] = 0;
}

__global__ void k_cvt(const float* __restrict__ x, const float* __restrict__ W1) {
    int t = blockIdx.x * blockDim.x + threadIdx.x;
    const int NX = NN * FEAT / 2;           // half2 count for x
    const int NW = FEAT * HC / 2;
    if (t < NX) {
        float2 v = *(const float2*)&x[t * 2];
        *(__half2*)&g_xh[t * 2] = __float22half2_rn(v);
    } else if (t < NX + NW) {
        int u = t - NX;
        float2 v = *(const float2*)&W1[u * 2];
        *(__half2*)&g_w1h[u * 2] = __float22half2_rn(v);
    }
}

// ---------------- CSR build ----------------
__global__ void k_count(const int* __restrict__ ei) {
    int t = blockIdx.x * blockDim.x + threadIdx.x;
    int e0 = t * 4;
    if (e0 >= TOT) return;
    if (e0 + 3 < E_IN) {
        int4 d4 = *(const int4*)&ei[E_IN + e0];
        atomicAdd(&g_cnt[d4.x], 1);
        atomicAdd(&g_cnt[d4.y], 1);
        atomicAdd(&g_cnt[d4.z], 1);
        atomicAdd(&g_cnt[d4.w], 1);
    } else {
        for (int k = 0; k < 4 && e0 + k < TOT; k++)
            atomicAdd(&g_cnt[edge_dst(ei, e0 + k)], 1);
    }
}

// Chunked exclusive scan: thread t owns elements [t*CH, t*CH+CH).
__global__ void k_scan() {
    const int CH = (NN + 1023) / 1024;            // 20
    __shared__ int sm[1024];
    int tid = threadIdx.x;
    int base = tid * CH;

    int sum = 0;
    for (int j = 0; j < CH; j++) {
        int i = base + j;
        int idx = (i < NN) ? i : 0;
        int v = g_cnt[idx];
        if (i >= NN) v = 0;
        sum += v;
    }
    sm[tid] = sum;
    __syncthreads();

    for (int off = 1; off < 1024; off <<= 1) {
        int idx = (tid >= off) ? (tid - off) : tid;   // always valid
        int t2 = sm[idx];
        if (tid < off) t2 = 0;
        __syncthreads();
        sm[tid] += t2;
        __syncthreads();
    }

    int run = sm[tid] - sum;                      // exclusive prefix of this chunk
    for (int j = 0; j < CH; j++) {
        int i = base + j;
        if (i < NN) {
            g_rowptr[i] = run;
            g_cur[i] = run;
            run += g_cnt[i];
        }
    }
    if (tid == 1023) g_rowptr[NN] = sm[1023];
}

__global__ void k_scatter(const int* __restrict__ ei) {
    int t = blockIdx.x * blockDim.x + threadIdx.x;
    if (t >= TOT) return;
    int d = edge_dst(ei, t);
    int s = edge_src(ei, t);
    int pos = atomicAdd(&g_cur[d], 1);
    g_esrc[pos] = s;
}

// ---------------- GEMM1 (tensor core): xh @ W1h -> g_h1h + fused alpha1 ----------------
// 128x64 block tile, BK=32, 256 threads (8 warps), warp computes 32x32 via 2x2 wmma.
__global__ __launch_bounds__(256) void k_gemm1(const float* __restrict__ a1s,
                                               const float* __restrict__ a1d) {
    const int BM = 128, BN = 64, BK = 32;
    const int LDA = BK + 8;                 // half padding
    const int LDB = BN + 8;
    const int LDC = BN + 8;                 // float padding
    __shared__ __align__(16) __half Ah[BM * LDA];
    __shared__ __align__(16) __half Bh[BK * LDB];
    __shared__ __align__(16) float  Cs[BM * LDC];

    int tid = threadIdx.x;
    int wid = tid >> 5;
    int row0 = blockIdx.x * BM;
    int col0 = blockIdx.y * BN;
    int wm = (wid & 3) * 32;                // warp row base in tile
    int wn = (wid >> 2) * 32;               // warp col base in tile

    wmma::fragment<wmma::accumulator, 16, 16, 16, float> acc[2][2];
#pragma unroll
    for (int i = 0; i < 2; i++)
#pragma unroll
        for (int j = 0; j < 2; j++)
            wmma::fill_fragment(acc[i][j], 0.0f);

    for (int k0 = 0; k0 < FEAT; k0 += BK) {
        // load A tile: 128 rows x 32 halves; 512 uint4 (8 halves each); 2 per thread
#pragma unroll
        for (int q = 0; q < 2; q++) {
            int li = tid * 2 + q;           // 0..511
            int r = li >> 2;                // 0..127
            int c8 = li & 3;                // 0..3 (8-half chunks)
            int gr = row0 + r;
            if (gr > NN - 1) gr = NN - 1;
            *(uint4*)&Ah[r * LDA + c8 * 8] = *(const uint4*)&g_xh[gr * FEAT + k0 + c8 * 8];
        }
        // load B tile: 32 rows x 64 halves; 256 uint4; 1 per thread
        {
            int r = tid >> 3;               // 0..31
            int c8 = tid & 7;               // 0..7
            *(uint4*)&Bh[r * LDB + c8 * 8] = *(const uint4*)&g_w1h[(k0 + r) * HC + col0 + c8 * 8];
        }
        __syncthreads();
#pragma unroll
        for (int kk = 0; kk < BK; kk += 16) {
            wmma::fragment<wmma::matrix_a, 16, 16, 16, __half, wmma::row_major> af[2];
            wmma::fragment<wmma::matrix_b, 16, 16, 16, __half, wmma::row_major> bf[2];
#pragma unroll
            for (int i = 0; i < 2; i++)
                wmma::load_matrix_sync(af[i], &Ah[(wm + i * 16) * LDA + kk], LDA);
#pragma unroll
            for (int j = 0; j < 2; j++)
                wmma::load_matrix_sync(bf[j], &Bh[kk * LDB + wn + j * 16], LDB);
#pragma unroll
            for (int i = 0; i < 2; i++)
#pragma unroll
                for (int j = 0; j < 2; j++)
                    wmma::mma_sync(acc[i][j], af[i], bf[j], acc[i][j]);
        }
        __syncthreads();
    }

    // dump accumulators to shared
#pragma unroll
    for (int i = 0; i < 2; i++)
#pragma unroll
        for (int j = 0; j < 2; j++)
            wmma::store_matrix_sync(&Cs[(wm + i * 16) * LDC + wn + j * 16], acc[i][j],
                                    LDC, wmma::mem_row_major);
    __syncthreads();

    // epilogue: thread t owns (row r = t>>1, head-half hh = t&1): 32 channels.
    {
        int r = tid >> 1;
        int hh = tid & 1;
        int gr = row0 + r;
        int h = blockIdx.y * 2 + hh;
        const float* crow = &Cs[r * LDC + hh * 32];
        if (gr < NN) {
            float ps = 0.0f, pd = 0.0f;
            const float* avs = &a1s[h * HID];
            const float* avd = &a1d[h * HID];
            __half2 hbuf[16];
#pragma unroll
            for (int c = 0; c < 32; c += 2) {
                float v0 = crow[c], v1 = crow[c + 1];
                ps += v0 * avs[c] + v1 * avs[c + 1];
                pd += v0 * avd[c] + v1 * avd[c + 1];
                hbuf[c >> 1] = __float22half2_rn(make_float2(v0, v1));
            }
            g_as1[gr * HEADS + h] = ps;
            g_ad1[gr * HEADS + h] = pd;
            __half2* hp = (__half2*)&g_h1h[gr * HC + h * HID];
#pragma unroll
            for (int c = 0; c < 16; c += 4)
                *(uint4*)&hp[c] = *(uint4*)&hbuf[c];
        }
    }
}

// ---------------- GEMM2: g_h2 @ W2 -> g_g2 (fp32) + g_g2h (fp16) ----------------
__global__ __launch_bounds__(320) void k_gemm2(const float* __restrict__ B) {
    const int BM = 128, BN = 40, BK = 16, NT = 320;
    __shared__ __align__(16) float As[BK][BM];   // transposed
    __shared__ __align__(16) float Bs[BK][BN];
    int tid = threadIdx.x;
    int tn = tid % 10;          // 0..9  : column group (4 cols)
    int tm = tid / 10;          // 0..31 : row group (4 rows)
    int row0 = blockIdx.x * BM;
    float acc[4][4] = {};

    for (int k0 = 0; k0 < HC; k0 += BK) {
        for (int li = tid; li < 512; li += NT) {
            int r = li >> 2;
            int c4 = li & 3;
            int gr = row0 + r;
            if (gr > NN - 1) gr = NN - 1;
            float4 v = *(const float4*)&g_h2[gr * HC + k0 + c4 * 4];
            As[c4 * 4 + 0][r] = v.x;
            As[c4 * 4 + 1][r] = v.y;
            As[c4 * 4 + 2][r] = v.z;
            As[c4 * 4 + 3][r] = v.w;
        }
        for (int li = tid; li < 160; li += NT) {
            int r = li / 10;
            int c4 = li % 10;
            *(float4*)&Bs[r][c4 * 4] = *(const float4*)&B[(k0 + r) * CLS + c4 * 4];
        }
        __syncthreads();
#pragma unroll
        for (int k = 0; k < BK; k++) {
            float a[4], b[4];
            *(float4*)&a[0] = *(const float4*)&As[k][tm * 4];
            *(float4*)&b[0] = *(const float4*)&Bs[k][tn * 4];
#pragma unroll
            for (int i = 0; i < 4; i++)
#pragma unroll
                for (int j = 0; j < 4; j++)
                    acc[i][j] += a[i] * b[j];
        }
        __syncthreads();
    }
#pragma unroll
    for (int i = 0; i < 4; i++) {
        int gr = row0 + tm * 4 + i;
        if (gr < NN) {
            *(float4*)&g_g2[gr * CLS + tn * 4] =
                make_float4(acc[i][0], acc[i][1], acc[i][2], acc[i][3]);
            __half2* hp = (__half2*)&g_g2h[gr * CLS + tn * 4];
            hp[0] = __float22half2_rn(make_float2(acc[i][0], acc[i][1]));
            hp[1] = __float22half2_rn(make_float2(acc[i][2], acc[i][3]));
        }
    }
}

// ---------------- layer1: online softmax + fp16 gather + bias + ELU ----------------
__global__ __launch_bounds__(128) void k_agg1(const float* __restrict__ b1) {
    int n = blockIdx.x;
    int wp = threadIdx.x >> 5;          // 0..3
    int lane = threadIdx.x & 31;
    int hl = lane >> 4;                 // head within pair
    int h = wp * 2 + hl;
    int el = lane & 15;                 // edge slot within 16-edge chunk
    int beg = g_rowptr[n], end = g_rowptr[n + 1];
    float ad = g_ad1[n * HEADS + h];
    const __half2* __restrict__ h1h2 = (const __half2*)g_h1h;

    float m = -INFINITY, ssum = 0.0f;
    float2 acc = make_float2(0.0f, 0.0f);
    for (int i0 = beg; i0 < end; i0 += 16) {
        int i = i0 + el;
        int sl = 0;
        float e = -INFINITY;
        if (i < end) {
            sl = g_esrc[i];
            e = lrelu(g_as1[sl * HEADS + h] + ad);
        }
        float cm = e;
#pragma unroll
        for (int o = 8; o; o >>= 1) cm = fmaxf(cm, __shfl_xor_sync(0xffffffffu, cm, o));
        float mn = fmaxf(m, cm);
        float sc = __expf(m - mn);
        acc.x *= sc; acc.y *= sc; ssum *= sc;
        m = mn;
        float w = (i < end) ? __expf(e - mn) : 0.0f;
        float ws = w;
#pragma unroll
        for (int o = 8; o; o >>= 1) ws += __shfl_xor_sync(0xffffffffu, ws, o);
        ssum += ws;
        int lim = min(16, end - i0);
        for (int j = 0; j < lim; j++) {
            int   s2 = __shfl_sync(0xffffffffu, sl, j);
            float wj = __shfl_sync(0xffffffffu, w, j + (hl << 4));
            float2 v = __half22float2(h1h2[s2 * (HC / 2) + wp * 32 + lane]);
            acc.x += wj * v.x;
            acc.y += wj * v.y;
        }
    }
    int c0 = wp * 64 + lane * 2;
    float inv_s = 1.0f / ssum;
    float o0 = acc.x * inv_s + b1[c0];
    float o1 = acc.y * inv_s + b1[c0 + 1];
    g_h2[n * HC + c0]     = (o0 > 0.0f) ? o0 : (__expf(o0) - 1.0f);
    g_h2[n * HC + c0 + 1] = (o1 > 0.0f) ? o1 : (__expf(o1) - 1.0f);
}

// ---------------- layer2 alpha projections (from fp32 g_g2) ----------------
__global__ void k_alpha2(const float* __restrict__ a2s, const float* __restrict__ a2d) {
    int n = blockIdx.x * blockDim.x + threadIdx.x;
    if (n >= NN) return;
    const float* gp = &g_g2[n * CLS];
    float accS = 0.0f, accD = 0.0f;
#pragma unroll
    for (int c = 0; c < CLS; c++) {
        float gv = gp[c];
        accS += gv * a2s[c];
        accD += gv * a2d[c];
    }
    g_as2[n] = accS;
    g_ad2[n] = accD;
}

// ---------------- layer2: online softmax + fp16 gather + bias + log_softmax ----------------
__global__ void k_agg2(const float* __restrict__ b2, float* __restrict__ out) {
    int n = blockIdx.x;
    int t = threadIdx.x;
    __shared__ float red[64];
    __shared__ int   s_src[64];
    __shared__ float s_w[64];
    __shared__ float o40[CLS];
    int beg = g_rowptr[n], end = g_rowptr[n + 1];
    float ad = g_ad2[n];
    const __half2* __restrict__ g2h2 = (const __half2*)g_g2h;

    float m = -INFINITY, ssum = 0.0f;
    float2 acc = make_float2(0.0f, 0.0f);
    for (int i0 = beg; i0 < end; i0 += 64) {
        int i = i0 + t;
        int s = 0;
        float e = -INFINITY;
        if (i < end) {
            s = g_esrc[i];
            e = lrelu(g_as2[s] + ad);
        }
        red[t] = e; __syncthreads();
        for (int off = 32; off; off >>= 1) { if (t < off) red[t] = fmaxf(red[t], red[t + off]); __syncthreads(); }
        float mn = fmaxf(m, red[0]);
        __syncthreads();
        float scale = __expf(m - mn);
        acc.x *= scale; acc.y *= scale;
        ssum *= scale;
        m = mn;
        float w = (i < end) ? __expf(e - mn) : 0.0f;
        s_src[t] = s;
        s_w[t] = w;
        red[t] = w; __syncthreads();
        for (int off = 32; off; off >>= 1) { if (t < off) red[t] += red[t + off]; __syncthreads(); }
        ssum += red[0];
        __syncthreads();
        int lim = min(64, end - i0);
        if (t < CLS / 2)
            for (int j = 0; j < lim; j++) {
                float2 v = __half22float2(g2h2[s_src[j] * (CLS / 2) + t]);
                acc.x += s_w[j] * v.x;
                acc.y += s_w[j] * v.y;
            }
        __syncthreads();
    }

    if (t < CLS / 2) {
        float inv_s = 1.0f / ssum;
        o40[t * 2]     = acc.x * inv_s + b2[t * 2];
        o40[t * 2 + 1] = acc.y * inv_s + b2[t * 2 + 1];
    }
    __syncthreads();
    float o = (t < CLS) ? o40[t] : -INFINITY;
    red[t] = o; __syncthreads();
    for (int off = 32; off; off >>= 1) { if (t < off) red[t] = fmaxf(red[t], red[t + off]); __syncthreads(); }
    float mx = red[0]; __syncthreads();
    red[t] = (t < CLS) ? __expf(o - mx) : 0.0f;
    __syncthreads();
    for (int off = 32; off; off >>= 1) { if (t < off) red[t] += red[t + off]; __syncthreads(); }
    if (t < CLS) out[n * CLS + t] = o - mx - logf(red[0]);
}

// ---------------- launch ----------------
extern "C" void kernel_launch(void* const* d_in, const int* in_sizes, int n_in,
                              void* d_out, int out_size) {
    const float* x   = (const float*)d_in[0];
    const int*   ei  = (const int*)d_in[1];      // edge_index is int32 (JAX x64 disabled)
    const float* W1  = (const float*)d_in[2];
    const float* a1s = (const float*)d_in[3];
    const float* a1d = (const float*)d_in[4];
    const float* b1  = (const float*)d_in[5];
    const float* W2  = (const float*)d_in[6];
    const float* a2s = (const float*)d_in[7];
    const float* a2d = (const float*)d_in[8];
    const float* b2  = (const float*)d_in[9];
    float*       out = (float*)d_out;

    // prep: CSR build + fp16 conversion
    k_init<<<(NN + 255) / 256, 256>>>();
    k_cvt<<<((NN * FEAT + FEAT * HC) / 2 + 255) / 256, 256>>>(x, W1);
    k_count<<<(TOT / 4 + 255) / 256, 256>>>(ei);
    k_scan<<<1, 1024>>>();
    k_scatter<<<(TOT + 255) / 256, 256>>>(ei);

    // layer 1
    k_gemm1<<<dim3((NN + 127) / 128, HC / 64), 256>>>(a1s, a1d);
    k_agg1<<<NN, 128>>>(b1);

    // layer 2
    k_gemm2<<<(NN + 127) / 128, 320>>>(W2);
    k_alpha2<<<(NN + 255) / 256, 256>>>(a2s, a2d);
    k_agg2<<<NN, 64>>>(b2, out);
}

// round 11
// speedup vs baseline: 2.2762x; 1.2638x over previous
#include <cuda_runtime.h>
#include <cuda_fp16.h>
#include <mma.h>
#include <math.h>

using namespace nvcuda;

#define NN 20000
#define FEAT 128
#define HID 32
#define HEADS 8
#define HC 256          // HEADS*HID
#define CLS 40
#define CLSP 64         // padded cols for tensor GEMM2
#define E_IN 640000
#define TOT (E_IN + NN)
#define NEG 0.2f
#define NB ((NN + 255) / 256)   // 79 scan blocks

// ---------------- scratch (device globals; no allocation allowed) ----------------
__device__ __half g_xh[NN * FEAT];     // x in fp16
__device__ __half g_w1h[FEAT * HC];    // W1 in fp16
__device__ __half g_w2h[HC * CLSP];    // W2 in fp16, zero-padded to 64 cols
__device__ __half g_h1h[NN * HC];      // layer1 linear output (fp16, for gather)
__device__ __half g_h2h[NN * HC];      // layer1 GAT output after ELU (fp16)
__device__ float  g_as1[NN * HEADS];
__device__ float  g_ad1[NN * HEADS];
__device__ float  g_g2[NN * CLS];      // layer2 linear output (fp32)
__device__ __half g_g2h[NN * CLS];     // layer2 linear output (fp16, for gather)
__device__ float  g_as2[NN];
__device__ float  g_ad2[NN];
__device__ int    g_rowptr[NN + 1];
__device__ int    g_cnt[NN];
__device__ int    g_cur[NN];
__device__ int    g_bsum[128];
__device__ int    g_boff[128];
__device__ int    g_esrc[TOT];         // src node per CSR slot (sorted by dst)

// ---------------- helpers (edge_index is INT32; loads always in-bounds) ----------------
__device__ __forceinline__ int edge_src(const int* ei, int e) {
    int idx = (e < E_IN) ? e : 0;
    int v = ei[idx];
    return (e < E_IN) ? v : (e - E_IN);
}
__device__ __forceinline__ int edge_dst(const int* ei, int e) {
    int idx = (e < E_IN) ? (E_IN + e) : 0;
    int v = ei[idx];
    return (e < E_IN) ? v : (e - E_IN);
}
__device__ __forceinline__ float lrelu(float v) { return v > 0.0f ? v : NEG * v; }

// ---------------- init + fp16 conversion ----------------
__global__ void k_init() {
    int t = blockIdx.x * blockDim.x + threadIdx.x;
    if (t < NN) g_cnt[t] = 0;
}

__global__ void k_cvt(const float* __restrict__ x, const float* __restrict__ W1,
                      const float* __restrict__ W2) {
    int t = blockIdx.x * blockDim.x + threadIdx.x;
    const int NX = NN * FEAT / 2;           // half2 units of x
    const int NW = FEAT * HC / 2;           // half2 units of W1
    const int NW2 = HC * CLSP / 2;          // half2 units of padded W2
    if (t < NX) {
        float2 v = *(const float2*)&x[t * 2];
        *(__half2*)&g_xh[t * 2] = __float22half2_rn(v);
    } else if (t < NX + NW) {
        int u = t - NX;
        float2 v = *(const float2*)&W1[u * 2];
        *(__half2*)&g_w1h[u * 2] = __float22half2_rn(v);
    } else if (t < NX + NW + NW2) {
        int u = t - NX - NW;
        int row = u / (CLSP / 2);
        int cp = (u % (CLSP / 2)) * 2;
        float v0 = (cp < CLS) ? W2[row * CLS + cp] : 0.0f;
        float v1 = (cp + 1 < CLS) ? W2[row * CLS + cp + 1] : 0.0f;
        *(__half2*)&g_w2h[u * 2] = __float22half2_rn(make_float2(v0, v1));
    }
}

// ---------------- CSR build ----------------
__global__ void k_count(const int* __restrict__ ei) {
    int t = blockIdx.x * blockDim.x + threadIdx.x;
    int e0 = t * 4;
    if (e0 >= TOT) return;
    if (e0 + 3 < E_IN) {
        int4 d4 = *(const int4*)&ei[E_IN + e0];
        atomicAdd(&g_cnt[d4.x], 1);
        atomicAdd(&g_cnt[d4.y], 1);
        atomicAdd(&g_cnt[d4.z], 1);
        atomicAdd(&g_cnt[d4.w], 1);
    } else {
        for (int k = 0; k < 4 && e0 + k < TOT; k++)
            atomicAdd(&g_cnt[edge_dst(ei, e0 + k)], 1);
    }
}

// Multi-block scan, phase 1: per-block sums of 256 counts
__global__ void k_bsum() {
    __shared__ int sm[256];
    int t = threadIdx.x;
    int i = blockIdx.x * 256 + t;
    int v = (i < NN) ? g_cnt[i] : 0;
    sm[t] = v;
    __syncthreads();
    for (int off = 128; off; off >>= 1) {
        if (t < off) sm[t] += sm[t + off];
        __syncthreads();
    }
    if (t == 0) g_bsum[blockIdx.x] = sm[0];
}

// phase 2: scan NB block sums (single block of 128)
__global__ void k_bscan() {
    __shared__ int sm[128];
    int t = threadIdx.x;
    int v = (t < NB) ? g_bsum[t] : 0;
    sm[t] = v;
    __syncthreads();
    for (int off = 1; off < 128; off <<= 1) {
        int idx = (t >= off) ? (t - off) : t;
        int add = sm[idx];
        if (t < off) add = 0;
        __syncthreads();
        sm[t] += add;
        __syncthreads();
    }
    if (t < NB) g_boff[t] = sm[t] - v;     // exclusive
    if (t == 127) g_rowptr[NN] = sm[127];
}

// phase 3: per-block exclusive scan + global offset -> rowptr/cur
__global__ void k_writeptr() {
    __shared__ int sm[256];
    int t = threadIdx.x;
    int i = blockIdx.x * 256 + t;
    int v = (i < NN) ? g_cnt[i] : 0;
    sm[t] = v;
    __syncthreads();
    for (int off = 1; off < 256; off <<= 1) {
        int idx = (t >= off) ? (t - off) : t;
        int add = sm[idx];
        if (t < off) add = 0;
        __syncthreads();
        sm[t] += add;
        __syncthreads();
    }
    if (i < NN) {
        int excl = sm[t] - v + g_boff[blockIdx.x];
        g_rowptr[i] = excl;
        g_cur[i] = excl;
    }
}

__global__ void k_scatter(const int* __restrict__ ei) {
    int t = blockIdx.x * blockDim.x + threadIdx.x;
    if (t >= TOT) return;
    int d = edge_dst(ei, t);
    int s = edge_src(ei, t);
    int pos = atomicAdd(&g_cur[d], 1);
    g_esrc[pos] = s;
}

// ---------------- GEMM1 (tensor core): xh @ W1h -> g_h1h + fused alpha1 ----------------
__global__ __launch_bounds__(256) void k_gemm1(const float* __restrict__ a1s,
                                               const float* __restrict__ a1d) {
    const int BM = 128, BN = 64, BK = 32;
    const int LDA = BK + 8;
    const int LDB = BN + 8;
    const int LDC = BN + 8;
    __shared__ __align__(16) __half Ah[BM * LDA];
    __shared__ __align__(16) __half Bh[BK * LDB];
    __shared__ __align__(16) float  Cs[BM * LDC];

    int tid = threadIdx.x;
    int wid = tid >> 5;
    int row0 = blockIdx.x * BM;
    int col0 = blockIdx.y * BN;
    int wm = (wid & 3) * 32;
    int wn = (wid >> 2) * 32;

    wmma::fragment<wmma::accumulator, 16, 16, 16, float> acc[2][2];
#pragma unroll
    for (int i = 0; i < 2; i++)
#pragma unroll
        for (int j = 0; j < 2; j++)
            wmma::fill_fragment(acc[i][j], 0.0f);

    for (int k0 = 0; k0 < FEAT; k0 += BK) {
#pragma unroll
        for (int q = 0; q < 2; q++) {
            int li = tid * 2 + q;
            int r = li >> 2;
            int c8 = li & 3;
            int gr = row0 + r;
            if (gr > NN - 1) gr = NN - 1;
            *(uint4*)&Ah[r * LDA + c8 * 8] = *(const uint4*)&g_xh[gr * FEAT + k0 + c8 * 8];
        }
        {
            int r = tid >> 3;
            int c8 = tid & 7;
            *(uint4*)&Bh[r * LDB + c8 * 8] = *(const uint4*)&g_w1h[(k0 + r) * HC + col0 + c8 * 8];
        }
        __syncthreads();
#pragma unroll
        for (int kk = 0; kk < BK; kk += 16) {
            wmma::fragment<wmma::matrix_a, 16, 16, 16, __half, wmma::row_major> af[2];
            wmma::fragment<wmma::matrix_b, 16, 16, 16, __half, wmma::row_major> bf[2];
#pragma unroll
            for (int i = 0; i < 2; i++)
                wmma::load_matrix_sync(af[i], &Ah[(wm + i * 16) * LDA + kk], LDA);
#pragma unroll
            for (int j = 0; j < 2; j++)
                wmma::load_matrix_sync(bf[j], &Bh[kk * LDB + wn + j * 16], LDB);
#pragma unroll
            for (int i = 0; i < 2; i++)
#pragma unroll
                for (int j = 0; j < 2; j++)
                    wmma::mma_sync(acc[i][j], af[i], bf[j], acc[i][j]);
        }
        __syncthreads();
    }

#pragma unroll
    for (int i = 0; i < 2; i++)
#pragma unroll
        for (int j = 0; j < 2; j++)
            wmma::store_matrix_sync(&Cs[(wm + i * 16) * LDC + wn + j * 16], acc[i][j],
                                    LDC, wmma::mem_row_major);
    __syncthreads();

    // epilogue: thread owns (row, head-half): 32 channels of one head
    {
        int r = tid >> 1;
        int hh = tid & 1;
        int gr = row0 + r;
        int h = blockIdx.y * 2 + hh;
        const float* crow = &Cs[r * LDC + hh * 32];
        if (gr < NN) {
            float ps = 0.0f, pd = 0.0f;
            const float* avs = &a1s[h * HID];
            const float* avd = &a1d[h * HID];
            __half2 hbuf[16];
#pragma unroll
            for (int c = 0; c < 32; c += 2) {
                float v0 = crow[c], v1 = crow[c + 1];
                ps += v0 * avs[c] + v1 * avs[c + 1];
                pd += v0 * avd[c] + v1 * avd[c + 1];
                hbuf[c >> 1] = __float22half2_rn(make_float2(v0, v1));
            }
            g_as1[gr * HEADS + h] = ps;
            g_ad1[gr * HEADS + h] = pd;
            __half2* hp = (__half2*)&g_h1h[gr * HC + h * HID];
#pragma unroll
            for (int c = 0; c < 16; c += 4)
                *(uint4*)&hp[c] = *(uint4*)&hbuf[c];
        }
    }
}

// ---------------- GEMM2 (tensor core): g_h2h @ W2h -> g_g2/g_g2h + fused alpha2 ----------------
__global__ __launch_bounds__(256) void k_gemm2(const float* __restrict__ a2s,
                                               const float* __restrict__ a2d) {
    const int BM = 128, BN = 64, BK = 32;
    const int LDA = BK + 8;
    const int LDB = BN + 8;
    const int LDC = BN + 8;
    __shared__ __align__(16) __half Ah[BM * LDA];
    __shared__ __align__(16) __half Bh[BK * LDB];
    __shared__ __align__(16) float  Cs[BM * LDC];

    int tid = threadIdx.x;
    int wid = tid >> 5;
    int row0 = blockIdx.x * BM;
    int wm = (wid & 3) * 32;
    int wn = (wid >> 2) * 32;

    wmma::fragment<wmma::accumulator, 16, 16, 16, float> acc[2][2];
#pragma unroll
    for (int i = 0; i < 2; i++)
#pragma unroll
        for (int j = 0; j < 2; j++)
            wmma::fill_fragment(acc[i][j], 0.0f);

    for (int k0 = 0; k0 < HC; k0 += BK) {
#pragma unroll
        for (int q = 0; q < 2; q++) {
            int li = tid * 2 + q;
            int r = li >> 2;
            int c8 = li & 3;
            int gr = row0 + r;
            if (gr > NN - 1) gr = NN - 1;
            *(uint4*)&Ah[r * LDA + c8 * 8] = *(const uint4*)&g_h2h[gr * HC + k0 + c8 * 8];
        }
        {
            int r = tid >> 3;
            int c8 = tid & 7;
            *(uint4*)&Bh[r * LDB + c8 * 8] = *(const uint4*)&g_w2h[(k0 + r) * CLSP + c8 * 8];
        }
        __syncthreads();
#pragma unroll
        for (int kk = 0; kk < BK; kk += 16) {
            wmma::fragment<wmma::matrix_a, 16, 16, 16, __half, wmma::row_major> af[2];
            wmma::fragment<wmma::matrix_b, 16, 16, 16, __half, wmma::row_major> bf[2];
#pragma unroll
            for (int i = 0; i < 2; i++)
                wmma::load_matrix_sync(af[i], &Ah[(wm + i * 16) * LDA + kk], LDA);
#pragma unroll
            for (int j = 0; j < 2; j++)
                wmma::load_matrix_sync(bf[j], &Bh[kk * LDB + wn + j * 16], LDB);
#pragma unroll
            for (int i = 0; i < 2; i++)
#pragma unroll
                for (int j = 0; j < 2; j++)
                    wmma::mma_sync(acc[i][j], af[i], bf[j], acc[i][j]);
        }
        __syncthreads();
    }

#pragma unroll
    for (int i = 0; i < 2; i++)
#pragma unroll
        for (int j = 0; j < 2; j++)
            wmma::store_matrix_sync(&Cs[(wm + i * 16) * LDC + wn + j * 16], acc[i][j],
                                    LDC, wmma::mem_row_major);
    __syncthreads();

    // epilogue: thread owns (row r = tid>>1, 20-col half part = tid&1)
    {
        int r = tid >> 1;
        int part = tid & 1;
        int gr = row0 + r;
        const float* crow = &Cs[r * LDC + part * 20];
        if (gr < NN) {
            float ps = 0.0f, pd = 0.0f;
#pragma unroll
            for (int c = 0; c < 20; c++) {
                float v = crow[c];
                int col = part * 20 + c;
                ps += v * a2s[col];
                pd += v * a2d[col];
                g_g2[gr * CLS + col] = v;
            }
#pragma unroll
            for (int c = 0; c < 20; c += 2) {
                *(__half2*)&g_g2h[gr * CLS + part * 20 + c] =
                    __float22half2_rn(make_float2(crow[c], crow[c + 1]));
            }
            ps += __shfl_xor_sync(0xffffffffu, ps, 1);
            pd += __shfl_xor_sync(0xffffffffu, pd, 1);
            if (part == 0) {
                g_as2[gr] = ps;
                g_ad2[gr] = pd;
            }
        } else {
            __shfl_xor_sync(0xffffffffu, 0.0f, 1);
            __shfl_xor_sync(0xffffffffu, 0.0f, 1);
        }
    }
}

// ---------------- layer1: online softmax + fp16 gather + bias + ELU -> g_h2h ----------------
__global__ __launch_bounds__(128) void k_agg1(const float* __restrict__ b1) {
    int n = blockIdx.x;
    int wp = threadIdx.x >> 5;          // 0..3
    int lane = threadIdx.x & 31;
    int hl = lane >> 4;                 // head within pair
    int h = wp * 2 + hl;
    int el = lane & 15;                 // edge slot within 16-edge chunk
    int beg = g_rowptr[n], end = g_rowptr[n + 1];
    float ad = g_ad1[n * HEADS + h];
    const __half2* __restrict__ h1h2 = (const __half2*)g_h1h;

    float m = -INFINITY, ssum = 0.0f;
    float2 acc = make_float2(0.0f, 0.0f);
    for (int i0 = beg; i0 < end; i0 += 16) {
        int i = i0 + el;
        int sl = 0;
        float e = -INFINITY;
        if (i < end) {
            sl = g_esrc[i];
            e = lrelu(g_as1[sl * HEADS + h] + ad);
        }
        float cm = e;
#pragma unroll
        for (int o = 8; o; o >>= 1) cm = fmaxf(cm, __shfl_xor_sync(0xffffffffu, cm, o));
        float mn = fmaxf(m, cm);
        float sc = __expf(m - mn);
        acc.x *= sc; acc.y *= sc; ssum *= sc;
        m = mn;
        float w = (i < end) ? __expf(e - mn) : 0.0f;
        float ws = w;
#pragma unroll
        for (int o = 8; o; o >>= 1) ws += __shfl_xor_sync(0xffffffffu, ws, o);
        ssum += ws;
        int lim = min(16, end - i0);
        for (int j = 0; j < lim; j++) {
            int   s2 = __shfl_sync(0xffffffffu, sl, j);
            float wj = __shfl_sync(0xffffffffu, w, j + (hl << 4));
            float2 v = __half22float2(h1h2[s2 * (HC / 2) + wp * 32 + lane]);
            acc.x += wj * v.x;
            acc.y += wj * v.y;
        }
    }
    int c0 = wp * 64 + lane * 2;
    float inv_s = 1.0f / ssum;
    float o0 = acc.x * inv_s + b1[c0];
    float o1 = acc.y * inv_s + b1[c0 + 1];
    o0 = (o0 > 0.0f) ? o0 : (__expf(o0) - 1.0f);
    o1 = (o1 > 0.0f) ? o1 : (__expf(o1) - 1.0f);
    *(__half2*)&g_h2h[n * HC + c0] = __float22half2_rn(make_float2(o0, o1));
}

// ---------------- layer2: online softmax + fp16 gather + bias + log_softmax ----------------
__global__ void k_agg2(const float* __restrict__ b2, float* __restrict__ out) {
    int n = blockIdx.x;
    int t = threadIdx.x;
    __shared__ float red[64];
    __shared__ int   s_src[64];
    __shared__ float s_w[64];
    __shared__ float o40[CLS];
    int beg = g_rowptr[n], end = g_rowptr[n + 1];
    float ad = g_ad2[n];
    const __half2* __restrict__ g2h2 = (const __half2*)g_g2h;

    float m = -INFINITY, ssum = 0.0f;
    float2 acc = make_float2(0.0f, 0.0f);
    for (int i0 = beg; i0 < end; i0 += 64) {
        int i = i0 + t;
        int s = 0;
        float e = -INFINITY;
        if (i < end) {
            s = g_esrc[i];
            e = lrelu(g_as2[s] + ad);
        }
        red[t] = e; __syncthreads();
        for (int off = 32; off; off >>= 1) { if (t < off) red[t] = fmaxf(red[t], red[t + off]); __syncthreads(); }
        float mn = fmaxf(m, red[0]);
        __syncthreads();
        float scale = __expf(m - mn);
        acc.x *= scale; acc.y *= scale;
        ssum *= scale;
        m = mn;
        float w = (i < end) ? __expf(e - mn) : 0.0f;
        s_src[t] = s;
        s_w[t] = w;
        red[t] = w; __syncthreads();
        for (int off = 32; off; off >>= 1) { if (t < off) red[t] += red[t + off]; __syncthreads(); }
        ssum += red[0];
        __syncthreads();
        int lim = min(64, end - i0);
        if (t < CLS / 2)
            for (int j = 0; j < lim; j++) {
                float2 v = __half22float2(g2h2[s_src[j] * (CLS / 2) + t]);
                acc.x += s_w[j] * v.x;
                acc.y += s_w[j] * v.y;
            }
        __syncthreads();
    }

    if (t < CLS / 2) {
        float inv_s = 1.0f / ssum;
        o40[t * 2]     = acc.x * inv_s + b2[t * 2];
        o40[t * 2 + 1] = acc.y * inv_s + b2[t * 2 + 1];
    }
    __syncthreads();
    float o = (t < CLS) ? o40[t] : -INFINITY;
    red[t] = o; __syncthreads();
    for (int off = 32; off; off >>= 1) { if (t < off) red[t] = fmaxf(red[t], red[t + off]); __syncthreads(); }
    float mx = red[0]; __syncthreads();
    red[t] = (t < CLS) ? __expf(o - mx) : 0.0f;
    __syncthreads();
    for (int off = 32; off; off >>= 1) { if (t < off) red[t] += red[t + off]; __syncthreads(); }
    if (t < CLS) out[n * CLS + t] = o - mx - logf(red[0]);
}

// ---------------- launch ----------------
extern "C" void kernel_launch(void* const* d_in, const int* in_sizes, int n_in,
                              void* d_out, int out_size) {
    const float* x   = (const float*)d_in[0];
    const int*   ei  = (const int*)d_in[1];      // edge_index is int32 (JAX x64 disabled)
    const float* W1  = (const float*)d_in[2];
    const float* a1s = (const float*)d_in[3];
    const float* a1d = (const float*)d_in[4];
    const float* b1  = (const float*)d_in[5];
    const float* W2  = (const float*)d_in[6];
    const float* a2s = (const float*)d_in[7];
    const float* a2d = (const float*)d_in[8];
    const float* b2  = (const float*)d_in[9];
    float*       out = (float*)d_out;

    // prep: fp16 conversion + CSR build (multi-block scan)
    k_init<<<(NN + 255) / 256, 256>>>();
    k_cvt<<<((NN * FEAT + FEAT * HC + HC * CLSP) / 2 + 255) / 256, 256>>>(x, W1, W2);
    k_count<<<(TOT / 4 + 255) / 256, 256>>>(ei);
    k_bsum<<<NB, 256>>>();
    k_bscan<<<1, 128>>>();
    k_writeptr<<<NB, 256>>>();
    k_scatter<<<(TOT + 255) / 256, 256>>>(ei);

    // layer 1
    k_gemm1<<<dim3((NN + 127) / 128, HC / 64), 256>>>(a1s, a1d);
    k_agg1<<<NN, 128>>>(b1);

    // layer 2
    k_gemm2<<<(NN + 127) / 128, 256>>>(a2s, a2d);
    k_agg2<<<NN, 64>>>(b2, out);
}